// round 12
// baseline (speedup 1.0000x reference)
#include <cuda_runtime.h>
#include <cuda_fp16.h>
#include <cstdint>

// ---------------------------------------------------------------------------
// GraphEncoder on GB300 (sm_103a) — fp16 mma.sync pipeline.
//
//   ds[i] = rsqrt(1 + rowsum(A)[i]);   xs = ds∘x  (fp16)
//   Z1  = ds∘(A@xs + xs)                     (agg, N=256)   [= nrm@x]
//   H   = relu(Z1@W1 + b1)                   (feature — smem only, fused)
//   P2  = ds∘(H@W2)                          (feature — fused kernel)
//   out = ds∘(A@P2 + P2) + b2                (agg, N=256)
//
// R11: agg kernel widened to 512 threads (16 warps, 4x4 grid of 32x64 warp
// tiles) to hide LDS->MMA latency (ncu: tensor 47%, occ 12% with 8 warps).
// Same 128x256 CTA tile, 4-stage 192KB ring. Fused feature kernel unchanged.
// ---------------------------------------------------------------------------

#define DEV_INLINE __device__ __forceinline__

static constexpr int BATCH = 8, NNODE = 4096, INC = 256, HIDC = 512, OUTC = 256;
static constexpr int MT = BATCH * NNODE;   // 32768

// Scratch (allocation-free __device__ globals)
__device__ float  g_ds [MT];
__device__ __half g_Ar [(size_t)BATCH * NNODE * NNODE];          // 256 MB
__device__ __half g_xs [(size_t)MT * INC];                       // plain
__device__ __half g_xst[(size_t)BATCH * INC * NNODE];            // T, interleaved
__device__ __half g_Z1 [(size_t)MT * INC];                       // interleaved
__device__ __half g_P2t[(size_t)BATCH * OUTC * NNODE];           // T, interleaved
__device__ __half g_P2 [(size_t)MT * OUTC];                      // plain
__device__ __half g_W1t[HIDC * INC];                             // interleaved K-major
__device__ __half g_W2t[OUTC * HIDC];                            // interleaved K-major

// ---------------------------------------------------------------------------
// helpers
// ---------------------------------------------------------------------------
DEV_INLINE int pos8(int p) { return ((p & 3) << 1) | ((p >> 2) & 1); }

DEV_INLINE void cp_async16(uint32_t saddr, const void* gmem) {
    asm volatile("cp.async.cg.shared.global [%0], [%1], 16;" :: "r"(saddr), "l"(gmem));
}
DEV_INLINE void cp_commit() { asm volatile("cp.async.commit_group;"); }
template <int N> DEV_INLINE void cp_wait() { asm volatile("cp.async.wait_group %0;" :: "n"(N)); }

DEV_INLINE uint32_t smem_u32(const void* p) {
    return (uint32_t)__cvta_generic_to_shared(p);
}

DEV_INLINE void lds64(uint32_t& x, uint32_t& y, uint32_t addr) {
    asm volatile("ld.shared.v2.b32 {%0, %1}, [%2];" : "=r"(x), "=r"(y) : "r"(addr));
}

DEV_INLINE void mma_f16(float* d, const uint32_t* a, const uint32_t* b) {
    asm volatile(
        "mma.sync.aligned.m16n8k16.row.col.f32.f16.f16.f32 "
        "{%0,%1,%2,%3},{%4,%5,%6,%7},{%8,%9},{%0,%1,%2,%3};"
        : "+f"(d[0]), "+f"(d[1]), "+f"(d[2]), "+f"(d[3])
        : "r"(a[0]), "r"(a[1]), "r"(a[2]), "r"(a[3]), "r"(b[0]), "r"(b[1]));
}

// ---------------------------------------------------------------------------
// prep_A: ds[row] = rsqrt(1+rowsum), Ar = fp16(A) pair-interleaved K-major
// ---------------------------------------------------------------------------
__global__ void __launch_bounds__(256) prep_A_kernel(const float* __restrict__ A,
                                                     __half* __restrict__ Ar,
                                                     float* __restrict__ ds) {
    __shared__ float srow[NNODE];
    long long row = blockIdx.x;
    const float4* p = (const float4*)(A + row * (long long)NNODE);
    float s = 0.f;
    #pragma unroll 2
    for (int i = threadIdx.x; i < NNODE / 4; i += 256) {
        float4 v = p[i];
        s += (v.x + v.y) + (v.z + v.w);
        *(float4*)(srow + 4 * i) = v;
    }
    #pragma unroll
    for (int o = 16; o; o >>= 1) s += __shfl_xor_sync(0xFFFFFFFFu, s, o);
    __shared__ float ws[8];
    if ((threadIdx.x & 31) == 0) ws[threadIdx.x >> 5] = s;
    __syncthreads();
    if (threadIdx.x == 0) {
        float tot = 0.f;
        #pragma unroll
        for (int i = 0; i < 8; i++) tot += ws[i];
        ds[row] = rsqrtf(tot + 1.0f);
    }
    int g = threadIdx.x;                  // 256 groups of 16 halfs
    const float* src = srow + 16 * g;
    __half2 ph[8];
    #pragma unroll
    for (int pp = 0; pp < 8; pp++)
        ph[pos8(pp)] = __floats2half2_rn(src[2 * pp], src[2 * pp + 1]);
    uint4* dst = (uint4*)(Ar + row * (long long)NNODE + 16 * g);
    dst[0] = *(uint4*)&ph[0];
    dst[1] = *(uint4*)&ph[4];
}

// ---------------------------------------------------------------------------
// prep_x: xs = fp16(ds∘x) plain row-major; xst = transposed, pair-interleaved
// ---------------------------------------------------------------------------
__global__ void __launch_bounds__(256) prep_x_kernel(const float* __restrict__ x,
                                                     const float* __restrict__ ds,
                                                     __half* __restrict__ xs,
                                                     __half* __restrict__ xst) {
    __shared__ __half sm[32][34];
    int m0 = blockIdx.x * 32, c0 = blockIdx.y * 32, b = blockIdx.z;
    #pragma unroll
    for (int r4 = 0; r4 < 4; r4++) {
        int idx = threadIdx.x + r4 * 256;
        int im = idx >> 5, ic = idx & 31;
        long long gm = (long long)b * NNODE + m0 + im;
        float v = x[gm * INC + c0 + ic] * ds[gm];
        __half h = __float2half_rn(v);
        sm[im][ic] = h;
        xs[gm * INC + c0 + ic] = h;
    }
    __syncthreads();
    #pragma unroll
    for (int r2 = 0; r2 < 2; r2++) {
        int pidx = threadIdx.x + r2 * 256;
        int jc = pidx >> 4, lp = pidx & 15;
        int grp = lp >> 3, pp = lp & 7;
        int mA = grp * 16 + 2 * pp;
        __half2 hv = __halves2half2(sm[mA][jc], sm[mA + 1][jc]);
        long long dst = (long long)b * INC * NNODE + (long long)(c0 + jc) * NNODE
                      + m0 + grp * 16 + pos8(pp) * 2;
        *(__half2*)(xst + dst) = hv;
    }
}

// ---------------------------------------------------------------------------
// prep_W_both: one launch for both weight transposes.
// ---------------------------------------------------------------------------
__global__ void __launch_bounds__(256) prep_W_both(const float* __restrict__ W1,
                                                   const float* __restrict__ W2,
                                                   __half* __restrict__ W1t,
                                                   __half* __restrict__ W2t) {
    int blk = blockIdx.x;
    const float* W; __half* Wt; int K, N, id;
    if (blk < 256) { W = W1; Wt = W1t; K = INC;  N = HIDC; id = blk * 256 + threadIdx.x; }
    else           { W = W2; Wt = W2t; K = HIDC; N = OUTC; id = (blk - 256) * 256 + threadIdx.x; }
    if (id >= N * (K / 2)) return;
    int n = id / (K / 2), pk = id % (K / 2);
    int grp = pk >> 3, pp = pk & 7;
    int k = 2 * pk;
    __half2 hv = __floats2half2_rn(W[(long long)k * N + n], W[(long long)(k + 1) * N + n]);
    *(__half2*)(Wt + (long long)n * K + grp * 16 + pos8(pp) * 2) = hv;
}

// ===========================================================================
// WIDE agg GEMM: C = A(MxK) @ B(NxK)^T, CTA 128x256, 512 threads =
// 16 warps (4x4) of 32x64, BK=64, 4-stage ring (192KB), occ 1.
//   EPI 0: Z1[m][n] = ds[m]*(acc + self[m][n])      -> half interleaved
//   EPI 3: out[m][n] = ds[m]*(acc + self[m][n]) + bias[n]  -> fp32
// ===========================================================================
static constexpr int WSTAGE = 49152;                 // A 16KB + B 32KB
static constexpr int WSMEM  = 4 * WSTAGE;            // 192 KB

template <int EPI>
__global__ void __launch_bounds__(512, 1) gemm_f16_wide(
    const __half* __restrict__ Ag, const __half* __restrict__ Bg, void* __restrict__ Cg,
    const __half* __restrict__ selfg, const float* __restrict__ ds,
    const float* __restrict__ bias,
    int K, long long lda, long long ldb, long long ldc, long long ldself,
    long long sAb, long long sBb, long long sCb, long long sSelfb) {

    extern __shared__ char smem[];
    const uint32_t sbase = smem_u32(smem);

    const int tid = threadIdx.x;
    const int b = blockIdx.z;
    const long long m0 = (long long)blockIdx.y * 128;
    const int n0 = blockIdx.x * 256;

    const __half* Ab = Ag + (long long)b * sAb;
    const __half* Bb = Bg + (long long)b * sBb;

    const int warp = tid >> 5, lane = tid & 31;
    const int gr = lane >> 2, t = lane & 3;
    const int mW = (warp >> 2) * 32, nW = (warp & 3) * 64;

    float acc[2][8][4];
    #pragma unroll
    for (int mi = 0; mi < 2; mi++)
        #pragma unroll
        for (int ni = 0; ni < 8; ni++)
            #pragma unroll
            for (int e = 0; e < 4; e++) acc[mi][ni][e] = 0.f;

    auto load_tile = [&](int st, int kt) {
        uint32_t sa = sbase + st * WSTAGE;
        #pragma unroll
        for (int i = 0; i < 2; i++) {                       // A: 1024 chunks
            int cq = tid + i * 512;
            int r = cq >> 3, c = cq & 7;
            const __half* g = Ab + (m0 + r) * lda + kt + c * 8;
            cp_async16(sa + r * 128 + ((c ^ (r & 7)) << 4), g);
        }
        uint32_t sb = sa + 16384;
        #pragma unroll
        for (int i = 0; i < 4; i++) {                       // B: 2048 chunks
            int cq = tid + i * 512;
            int r = cq >> 3, c = cq & 7;
            const __half* g = Bb + (long long)(n0 + r) * ldb + kt + c * 8;
            cp_async16(sb + r * 128 + ((c ^ (r & 7)) << 4), g);
        }
    };

    const int nK = K / 64;                                  // 64 for agg
    load_tile(0, 0); cp_commit();
    load_tile(1, 64); cp_commit();
    load_tile(2, 128); cp_commit();

    for (int tt = 0; tt < nK; tt++) {
        int rem = nK - 1 - tt;
        if (rem >= 2) cp_wait<2>(); else if (rem == 1) cp_wait<1>(); else cp_wait<0>();
        __syncthreads();
        if (tt + 3 < nK) { load_tile((tt + 3) & 3, (tt + 3) * 64); cp_commit(); }

        uint32_t sa = sbase + (tt & 3) * WSTAGE;
        uint32_t sb = sa + 16384;

        #pragma unroll
        for (int G = 0; G < 4; G++) {
            const int chunk = (G << 1) | (t >> 1);
            const uint32_t swo = ((chunk ^ gr) << 4) + ((t & 1) << 3);
            uint32_t a[2][4];
            #pragma unroll
            for (int mi = 0; mi < 2; mi++) {
                uint32_t ra = sa + (mW + mi * 16 + gr) * 128 + swo;
                lds64(a[mi][0], a[mi][2], ra);
                lds64(a[mi][1], a[mi][3], ra + 1024);
            }
            #pragma unroll
            for (int ni = 0; ni < 8; ni++) {
                uint32_t bf[2];
                lds64(bf[0], bf[1], sb + (nW + ni * 8 + gr) * 128 + swo);
                #pragma unroll
                for (int mi = 0; mi < 2; mi++)
                    mma_f16(acc[mi][ni], a[mi], bf);
            }
        }
    }
    __syncthreads();

    // ---------------- epilogue ----------------
    const __half* selfb = selfg + (long long)b * sSelfb;
    #pragma unroll
    for (int mi = 0; mi < 2; mi++) {
        #pragma unroll
        for (int rr = 0; rr < 2; rr++) {
            int m_loc = mW + mi * 16 + gr + rr * 8;
            long long m = m0 + m_loc;
            float d = ds[(long long)b * NNODE + m];
            #pragma unroll
            for (int ni = 0; ni < 8; ni++) {
                int col = n0 + nW + ni * 8 + 2 * t;
                float v0 = acc[mi][ni][rr * 2 + 0];
                float v1 = acc[mi][ni][rr * 2 + 1];
                float2 sv = __half22float2(*(const __half2*)(selfb + m * ldself + col));
                if (EPI == 0) {
                    v0 = d * (v0 + sv.x);
                    v1 = d * (v1 + sv.y);
                    int g16 = col >> 4, lp = (col >> 1) & 7;
                    __half* Ch = (__half*)Cg + (long long)b * sCb;
                    *(__half2*)(Ch + m * ldc + (g16 << 4) + (pos8(lp) << 1)) =
                        __floats2half2_rn(v0, v1);
                } else {  // EPI == 3
                    v0 = fmaf(d, v0 + sv.x, bias[col]);
                    v1 = fmaf(d, v1 + sv.y, bias[col + 1]);
                    float* Cf = (float*)Cg + (long long)b * sCb;
                    *(float2*)(Cf + m * ldc + col) = make_float2(v0, v1);
                }
            }
        }
    }
}

// ===========================================================================
// FUSED feature kernel (unchanged from R10): per CTA (128 rows):
//   H = relu(Z1_blk @ W1^T + b1) -> smem; P2 = ds∘(H @ W2^T); P2 + P2t out.
// 512 threads, occ 1, smem 224KB.
// ===========================================================================
static constexpr int FZ1 = 0;               // Z1: 4 stages x 16KB = 64KB
static constexpr int FH  = 65536;           // H : 8 stages x 16KB = 128KB
static constexpr int FWB = 196608;          // W1 stream: 2 x 16KB
static constexpr int FW2 = 0;               // W2 stream: 2 x 32KB (reuses Z1)
static constexpr int FSMEM = 229376;        // 224 KB

__global__ void __launch_bounds__(512, 1) gemm_feat(
    const __half* __restrict__ Z1, const __half* __restrict__ W1t,
    const __half* __restrict__ W2t, const float* __restrict__ b1,
    const float* __restrict__ ds,
    __half* __restrict__ P2t, __half* __restrict__ P2) {

    extern __shared__ char smem[];
    const uint32_t sbase = smem_u32(smem);
    const int tid = threadIdx.x;
    const long long m0 = (long long)blockIdx.x * 128;

    const int warp = tid >> 5, lane = tid & 31;
    const int gr = lane >> 2, t = lane & 3;

    // ---- load Z1 block: 128 rows x 512B into 4 BK64 stages ----
    #pragma unroll
    for (int i = 0; i < 8; i++) {
        int q = tid + i * 512;            // 0..4095 16B-chunks
        int r = q >> 5, c = q & 31;
        const __half* g = Z1 + (m0 + r) * INC + c * 8;
        uint32_t st = c >> 3, cc = c & 7;
        cp_async16(sbase + FZ1 + st * 16384 + r * 128 + ((cc ^ (r & 7)) << 4), g);
    }
    cp_commit();

    // ================= GEMM1: H chunks of 128 hidden =================
    {
        const int mW = (warp >> 2) * 32, nW = (warp & 3) * 32;
        for (int hc = 0; hc < 4; hc++) {
            float acc[2][4][4];
            #pragma unroll
            for (int mi = 0; mi < 2; mi++)
                #pragma unroll
                for (int ni = 0; ni < 4; ni++)
                    #pragma unroll
                    for (int e = 0; e < 4; e++) acc[mi][ni][e] = 0.f;

            auto loadW1 = [&](int buf, int kk) {
                #pragma unroll
                for (int i = 0; i < 2; i++) {
                    int q = tid + i * 512;     // 0..1023 chunks (128 rows x 8)
                    int r = q >> 3, c = q & 7;
                    const __half* g = W1t + (size_t)(hc * 128 + r) * INC + kk * 64 + c * 8;
                    cp_async16(sbase + FWB + buf * 16384 + r * 128 + ((c ^ (r & 7)) << 4), g);
                }
            };
            loadW1(0, 0); cp_commit();

            for (int kk = 0; kk < 4; kk++) {
                if (kk + 1 < 4) { loadW1((kk + 1) & 1, kk + 1); cp_commit(); cp_wait<1>(); }
                else cp_wait<0>();
                __syncthreads();
                uint32_t sa = sbase + FZ1 + kk * 16384;
                uint32_t sb = sbase + FWB + (kk & 1) * 16384;
                #pragma unroll
                for (int G = 0; G < 4; G++) {
                    const int chunk = (G << 1) | (t >> 1);
                    const uint32_t swo = ((chunk ^ gr) << 4) + ((t & 1) << 3);
                    uint32_t a[2][4];
                    #pragma unroll
                    for (int mi = 0; mi < 2; mi++) {
                        uint32_t ra = sa + (mW + mi * 16 + gr) * 128 + swo;
                        lds64(a[mi][0], a[mi][2], ra);
                        lds64(a[mi][1], a[mi][3], ra + 1024);
                    }
                    #pragma unroll
                    for (int ni = 0; ni < 4; ni++) {
                        uint32_t bf[2];
                        lds64(bf[0], bf[1], sb + (nW + ni * 8 + gr) * 128 + swo);
                        #pragma unroll
                        for (int mi = 0; mi < 2; mi++)
                            mma_f16(acc[mi][ni], a[mi], bf);
                    }
                }
                __syncthreads();
            }

            // epilogue hc: relu+bias -> fp16 -> H operand stages
            #pragma unroll
            for (int mi = 0; mi < 2; mi++) {
                #pragma unroll
                for (int rr = 0; rr < 2; rr++) {
                    int m_loc = mW + mi * 16 + gr + rr * 8;
                    #pragma unroll
                    for (int ni = 0; ni < 4; ni++) {
                        int nl = nW + ni * 8 + 2 * t;
                        int h = hc * 128 + nl;
                        float2 bb = *(const float2*)(b1 + h);
                        float v0 = fmaxf(acc[mi][ni][rr * 2 + 0] + bb.x, 0.f);
                        float v1 = fmaxf(acc[mi][ni][rr * 2 + 1] + bb.y, 0.f);
                        __half2 hv = __floats2half2_rn(v0, v1);
                        int sH = h >> 6, k64 = h & 63;
                        int s = (k64 >> 4) * 16 + pos8((k64 >> 1) & 7) * 2;
                        int cch = s >> 3;
                        int win = (2 * s) & 15;
                        uint32_t addr = sbase + FH + sH * 16384 + m_loc * 128
                                      + ((cch ^ (m_loc & 7)) << 4) + win;
                        asm volatile("st.shared.b32 [%0], %1;"
                                     :: "r"(addr), "r"(*(uint32_t*)&hv));
                    }
                }
            }
        }
    }
    __syncthreads();   // H complete; Z1 region free for W2 buffers

    // ================= GEMM2: P2 = H @ W2^T (K=512) =================
    const int mW2 = (warp >> 2) * 32, nW2 = (warp & 3) * 64;
    float acc2[2][8][4];
    #pragma unroll
    for (int mi = 0; mi < 2; mi++)
        #pragma unroll
        for (int ni = 0; ni < 8; ni++)
            #pragma unroll
            for (int e = 0; e < 4; e++) acc2[mi][ni][e] = 0.f;

    auto loadW2 = [&](int buf, int kk) {
        #pragma unroll
        for (int i = 0; i < 4; i++) {
            int q = tid + i * 512;             // 0..2047 chunks (256 rows x 8)
            int r = q >> 3, c = q & 7;
            const __half* g = W2t + (size_t)r * HIDC + kk * 64 + c * 8;
            cp_async16(sbase + FW2 + buf * 32768 + r * 128 + ((c ^ (r & 7)) << 4), g);
        }
    };
    loadW2(0, 0); cp_commit();

    for (int kk = 0; kk < 8; kk++) {
        if (kk + 1 < 8) { loadW2((kk + 1) & 1, kk + 1); cp_commit(); cp_wait<1>(); }
        else cp_wait<0>();
        __syncthreads();
        uint32_t sa = sbase + FH + kk * 16384;
        uint32_t sb = sbase + FW2 + (kk & 1) * 32768;
        #pragma unroll
        for (int G = 0; G < 4; G++) {
            const int chunk = (G << 1) | (t >> 1);
            const uint32_t swo = ((chunk ^ gr) << 4) + ((t & 1) << 3);
            uint32_t a[2][4];
            #pragma unroll
            for (int mi = 0; mi < 2; mi++) {
                uint32_t ra = sa + (mW2 + mi * 16 + gr) * 128 + swo;
                lds64(a[mi][0], a[mi][2], ra);
                lds64(a[mi][1], a[mi][3], ra + 1024);
            }
            #pragma unroll
            for (int ni = 0; ni < 8; ni++) {
                uint32_t bf[2];
                lds64(bf[0], bf[1], sb + (nW2 + ni * 8 + gr) * 128 + swo);
                #pragma unroll
                for (int mi = 0; mi < 2; mi++)
                    mma_f16(acc2[mi][ni], a[mi], bf);
            }
        }
        __syncthreads();
    }

    // ---------------- epilogue: P2 plain + staged transpose for P2t ----------------
    __half* sT = (__half*)(smem + FH);    // [256][136] halfs, reuses H region
    #pragma unroll
    for (int mi = 0; mi < 2; mi++) {
        #pragma unroll
        for (int rr = 0; rr < 2; rr++) {
            int m_loc = mW2 + mi * 16 + gr + rr * 8;
            long long m = m0 + m_loc;
            float d = ds[m];
            #pragma unroll
            for (int ni = 0; ni < 8; ni++) {
                int nl = nW2 + ni * 8 + 2 * t;
                float v0 = d * acc2[mi][ni][rr * 2 + 0];
                float v1 = d * acc2[mi][ni][rr * 2 + 1];
                __half2 hv = __floats2half2_rn(v0, v1);
                *(__half2*)(P2 + m * OUTC + nl) = hv;
                sT[nl * 136 + m_loc] = __low2half(hv);
                sT[(nl + 1) * 136 + m_loc] = __high2half(hv);
            }
        }
    }
    __syncthreads();

    // transposed interleaved writeout: thread = (n, m-half)
    {
        int n = tid & 255, mh = tid >> 8;       // mh in {0,1}
        int b = (int)(m0 >> 12);
        long long m0loc = m0 & 4095;
        __half* Ct = P2t + (size_t)b * OUTC * NNODE + (size_t)n * NNODE + m0loc + mh * 64;
        #pragma unroll
        for (int mg = 0; mg < 4; mg++) {
            __half2 ph[8];
            #pragma unroll
            for (int pp = 0; pp < 8; pp++) {
                int mA = mh * 64 + mg * 16 + 2 * pp;
                ph[pos8(pp)] = __halves2half2(sT[n * 136 + mA], sT[n * 136 + mA + 1]);
            }
            uint4* dst = (uint4*)(Ct + mg * 16);
            dst[0] = *(uint4*)&ph[0];
            dst[1] = *(uint4*)&ph[4];
        }
    }
}

// ---------------------------------------------------------------------------
// launch
// ---------------------------------------------------------------------------
extern "C" void kernel_launch(void* const* d_in, const int* in_sizes, int n_in,
                              void* d_out, int out_size) {
    const float* x  = (const float*)d_in[0];
    const float* A  = (const float*)d_in[1];
    const float* W1 = (const float*)d_in[2];
    const float* b1 = (const float*)d_in[3];
    const float* W2 = (const float*)d_in[4];
    const float* b2 = (const float*)d_in[5];
    float* out = (float*)d_out;

    float* ds;
    __half *Ar, *xs, *xst, *Z1, *P2t, *P2, *W1t, *W2t;
    cudaGetSymbolAddress((void**)&ds,  g_ds);
    cudaGetSymbolAddress((void**)&Ar,  g_Ar);
    cudaGetSymbolAddress((void**)&xs,  g_xs);
    cudaGetSymbolAddress((void**)&xst, g_xst);
    cudaGetSymbolAddress((void**)&Z1,  g_Z1);
    cudaGetSymbolAddress((void**)&P2t, g_P2t);
    cudaGetSymbolAddress((void**)&P2,  g_P2);
    cudaGetSymbolAddress((void**)&W1t, g_W1t);
    cudaGetSymbolAddress((void**)&W2t, g_W2t);

    cudaFuncSetAttribute(gemm_f16_wide<0>, cudaFuncAttributeMaxDynamicSharedMemorySize, WSMEM);
    cudaFuncSetAttribute(gemm_f16_wide<3>, cudaFuncAttributeMaxDynamicSharedMemorySize, WSMEM);
    cudaFuncSetAttribute(gemm_feat,        cudaFuncAttributeMaxDynamicSharedMemorySize, FSMEM);

    // prep
    prep_A_kernel<<<BATCH * NNODE, 256>>>(A, Ar, ds);
    prep_x_kernel<<<dim3(NNODE / 32, INC / 32, BATCH), 256>>>(x, ds, xs, xst);
    prep_W_both<<<512, 256>>>(W1, W2, W1t, W2t);

    // G1: Z1 = ds∘(A@xs + xs)   (wide agg, per-batch, N=256)
    gemm_f16_wide<0><<<dim3(INC / 256, NNODE / 128, BATCH), 512, WSMEM>>>(
        Ar, xst, Z1, xs, ds, nullptr,
        NNODE, NNODE, NNODE, INC, INC,
        (long long)NNODE * NNODE, (long long)INC * NNODE,
        (long long)NNODE * INC, (long long)NNODE * INC);

    // G2+G3 fused: H in smem, P2/P2t out
    gemm_feat<<<MT / 128, 512, FSMEM>>>(Z1, W1t, W2t, b1, ds, P2t, P2);

    // G4: out = ds∘(A@P2 + P2) + b2   (wide agg)
    gemm_f16_wide<3><<<dim3(OUTC / 256, NNODE / 128, BATCH), 512, WSMEM>>>(
        Ar, P2t, out, P2, ds, b2,
        NNODE, NNODE, NNODE, OUTC, OUTC,
        (long long)NNODE * NNODE, (long long)OUTC * NNODE,
        (long long)NNODE * OUTC, (long long)NNODE * OUTC);
}

// round 14
// speedup vs baseline: 1.2403x; 1.2403x over previous
#include <cuda_runtime.h>
#include <cuda_fp16.h>
#include <cstdint>

// ---------------------------------------------------------------------------
// GraphEncoder on GB300 (sm_103a) — fp16 mma.sync pipeline.
//
//   ds[i] = rsqrt(1 + rowsum(A)[i]);   xs = ds∘x  (fp16)
//   Z1  = ds∘(A@xs + xs)                     (agg, N=256)   [= nrm@x]
//   H   = relu(Z1@W1 + b1)                   (feature — smem only, fused)
//   P2  = ds∘(H@W2)                          (feature — fused kernel)
//   out = ds∘(A@P2 + P2) + b2                (agg, N=256)
//
// R12: agg mainloop rebuilt on ldmatrix.x4 (plain K-order operands, standard
// chunk swizzle) — 8 LDSM.x4 per G instead of 24 lds64, much less address
// ALU. Agg = 256 thr, 8 warps of 64x64, 4-stage 192KB ring (R10 shape).
// Fused feature kernel keeps the lds64/interleaved path (Z1/W1t/W2t/H).
// ---------------------------------------------------------------------------

#define DEV_INLINE __device__ __forceinline__

static constexpr int BATCH = 8, NNODE = 4096, INC = 256, HIDC = 512, OUTC = 256;
static constexpr int MT = BATCH * NNODE;   // 32768

// Scratch (allocation-free __device__ globals)
__device__ float  g_ds [MT];
__device__ __half g_Ar [(size_t)BATCH * NNODE * NNODE];          // 256 MB (plain fp16)
__device__ __half g_xs [(size_t)MT * INC];                       // plain
__device__ __half g_xst[(size_t)BATCH * INC * NNODE];            // T, plain
__device__ __half g_Z1 [(size_t)MT * INC];                       // interleaved (feat)
__device__ __half g_P2t[(size_t)BATCH * OUTC * NNODE];           // T, plain
__device__ __half g_P2 [(size_t)MT * OUTC];                      // plain
__device__ __half g_W1t[HIDC * INC];                             // interleaved K-major
__device__ __half g_W2t[OUTC * HIDC];                            // interleaved K-major

// ---------------------------------------------------------------------------
// helpers
// ---------------------------------------------------------------------------
DEV_INLINE int pos8(int p) { return ((p & 3) << 1) | ((p >> 2) & 1); }

DEV_INLINE void cp_async16(uint32_t saddr, const void* gmem) {
    asm volatile("cp.async.cg.shared.global [%0], [%1], 16;" :: "r"(saddr), "l"(gmem));
}
DEV_INLINE void cp_commit() { asm volatile("cp.async.commit_group;"); }
template <int N> DEV_INLINE void cp_wait() { asm volatile("cp.async.wait_group %0;" :: "n"(N)); }

DEV_INLINE uint32_t smem_u32(const void* p) {
    return (uint32_t)__cvta_generic_to_shared(p);
}

DEV_INLINE void lds64(uint32_t& x, uint32_t& y, uint32_t addr) {
    asm volatile("ld.shared.v2.b32 {%0, %1}, [%2];" : "=r"(x), "=r"(y) : "r"(addr));
}

DEV_INLINE void ldsm_x4(uint32_t* r, uint32_t addr) {
    asm volatile("ldmatrix.sync.aligned.m8n8.x4.shared.b16 {%0,%1,%2,%3}, [%4];"
                 : "=r"(r[0]), "=r"(r[1]), "=r"(r[2]), "=r"(r[3]) : "r"(addr));
}

DEV_INLINE void mma_f16(float* d, const uint32_t* a, const uint32_t* b) {
    asm volatile(
        "mma.sync.aligned.m16n8k16.row.col.f32.f16.f16.f32 "
        "{%0,%1,%2,%3},{%4,%5,%6,%7},{%8,%9},{%0,%1,%2,%3};"
        : "+f"(d[0]), "+f"(d[1]), "+f"(d[2]), "+f"(d[3])
        : "r"(a[0]), "r"(a[1]), "r"(a[2]), "r"(a[3]), "r"(b[0]), "r"(b[1]));
}

// ---------------------------------------------------------------------------
// prep_A: ds[row] = rsqrt(1+rowsum), Ar = fp16(A) PLAIN K-major
// ---------------------------------------------------------------------------
__global__ void __launch_bounds__(256) prep_A_kernel(const float* __restrict__ A,
                                                     __half* __restrict__ Ar,
                                                     float* __restrict__ ds) {
    __shared__ float srow[NNODE];
    long long row = blockIdx.x;
    const float4* p = (const float4*)(A + row * (long long)NNODE);
    float s = 0.f;
    #pragma unroll 2
    for (int i = threadIdx.x; i < NNODE / 4; i += 256) {
        float4 v = p[i];
        s += (v.x + v.y) + (v.z + v.w);
        *(float4*)(srow + 4 * i) = v;
    }
    #pragma unroll
    for (int o = 16; o; o >>= 1) s += __shfl_xor_sync(0xFFFFFFFFu, s, o);
    __shared__ float ws[8];
    if ((threadIdx.x & 31) == 0) ws[threadIdx.x >> 5] = s;
    __syncthreads();
    if (threadIdx.x == 0) {
        float tot = 0.f;
        #pragma unroll
        for (int i = 0; i < 8; i++) tot += ws[i];
        ds[row] = rsqrtf(tot + 1.0f);
    }
    int g = threadIdx.x;                  // 256 groups of 16 halfs
    const float* src = srow + 16 * g;
    __half2 ph[8];
    #pragma unroll
    for (int pp = 0; pp < 8; pp++)
        ph[pp] = __floats2half2_rn(src[2 * pp], src[2 * pp + 1]);   // plain
    uint4* dst = (uint4*)(Ar + row * (long long)NNODE + 16 * g);
    dst[0] = *(uint4*)&ph[0];
    dst[1] = *(uint4*)&ph[4];
}

// ---------------------------------------------------------------------------
// prep_x: xs = fp16(ds∘x) plain row-major; xst = transposed PLAIN
// ---------------------------------------------------------------------------
__global__ void __launch_bounds__(256) prep_x_kernel(const float* __restrict__ x,
                                                     const float* __restrict__ ds,
                                                     __half* __restrict__ xs,
                                                     __half* __restrict__ xst) {
    __shared__ __half sm[32][34];
    int m0 = blockIdx.x * 32, c0 = blockIdx.y * 32, b = blockIdx.z;
    #pragma unroll
    for (int r4 = 0; r4 < 4; r4++) {
        int idx = threadIdx.x + r4 * 256;
        int im = idx >> 5, ic = idx & 31;
        long long gm = (long long)b * NNODE + m0 + im;
        float v = x[gm * INC + c0 + ic] * ds[gm];
        __half h = __float2half_rn(v);
        sm[im][ic] = h;
        xs[gm * INC + c0 + ic] = h;
    }
    __syncthreads();
    #pragma unroll
    for (int r2 = 0; r2 < 2; r2++) {
        int pidx = threadIdx.x + r2 * 256;   // 512 = 32 ch * 16 pairs
        int jc = pidx >> 4, lp = pidx & 15;
        int mA = 2 * lp;
        __half2 hv = __halves2half2(sm[mA][jc], sm[mA + 1][jc]);
        long long dst = (long long)b * INC * NNODE + (long long)(c0 + jc) * NNODE
                      + m0 + mA;                       // plain
        *(__half2*)(xst + dst) = hv;
    }
}

// ---------------------------------------------------------------------------
// prep_W_both: one launch for both weight transposes (interleaved for feat).
// ---------------------------------------------------------------------------
__global__ void __launch_bounds__(256) prep_W_both(const float* __restrict__ W1,
                                                   const float* __restrict__ W2,
                                                   __half* __restrict__ W1t,
                                                   __half* __restrict__ W2t) {
    int blk = blockIdx.x;
    const float* W; __half* Wt; int K, N, id;
    if (blk < 256) { W = W1; Wt = W1t; K = INC;  N = HIDC; id = blk * 256 + threadIdx.x; }
    else           { W = W2; Wt = W2t; K = HIDC; N = OUTC; id = (blk - 256) * 256 + threadIdx.x; }
    if (id >= N * (K / 2)) return;
    int n = id / (K / 2), pk = id % (K / 2);
    int grp = pk >> 3, pp = pk & 7;
    int k = 2 * pk;
    __half2 hv = __floats2half2_rn(W[(long long)k * N + n], W[(long long)(k + 1) * N + n]);
    *(__half2*)(Wt + (long long)n * K + grp * 16 + pos8(pp) * 2) = hv;
}

// ===========================================================================
// WIDE agg GEMM (ldmatrix mainloop): C = A(MxK) @ B(NxK)^T, CTA 128x256,
// 256 threads = 8 warps (2x4) of 64x64, BK=64, 4-stage ring (192KB), occ 1.
//   EPI 0: Z1[m][n] = ds[m]*(acc + self[m][n])      -> half INTERLEAVED
//   EPI 3: out[m][n] = ds[m]*(acc + self[m][n]) + bias[n]  -> fp32
// ===========================================================================
static constexpr int WSTAGE = 49152;                 // A 16KB + B 32KB
static constexpr int WSMEM  = 4 * WSTAGE;            // 192 KB

template <int EPI>
__global__ void __launch_bounds__(256, 1) gemm_f16_wide(
    const __half* __restrict__ Ag, const __half* __restrict__ Bg, void* __restrict__ Cg,
    const __half* __restrict__ selfg, const float* __restrict__ ds,
    const float* __restrict__ bias,
    int K, long long lda, long long ldb, long long ldc, long long ldself,
    long long sAb, long long sBb, long long sCb, long long sSelfb) {

    extern __shared__ char smem[];
    const uint32_t sbase = smem_u32(smem);

    const int tid = threadIdx.x;
    const int b = blockIdx.z;
    const long long m0 = (long long)blockIdx.y * 128;
    const int n0 = blockIdx.x * 256;

    const __half* Ab = Ag + (long long)b * sAb;
    const __half* Bb = Bg + (long long)b * sBb;

    const int warp = tid >> 5, lane = tid & 31;
    const int gr = lane >> 2, t = lane & 3;
    const int mW = (warp >> 2) * 64, nW = (warp & 3) * 64;

    // ldmatrix per-lane mapping
    const int a_rl  = lane & 15;              // row within 16-row A tile
    const int a_cs  = lane >> 4;              // chunk select 0/1
    const int b_nl  = ((lane >> 4) << 3) + (lane & 7);   // row within 16-row B tile
    const int b_cs  = (lane >> 3) & 1;        // chunk select 0/1

    float acc[4][8][4];
    #pragma unroll
    for (int mi = 0; mi < 4; mi++)
        #pragma unroll
        for (int ni = 0; ni < 8; ni++)
            #pragma unroll
            for (int e = 0; e < 4; e++) acc[mi][ni][e] = 0.f;

    auto load_tile = [&](int st, int kt) {
        uint32_t sa = sbase + st * WSTAGE;
        #pragma unroll
        for (int i = 0; i < 4; i++) {                       // A: 1024 chunks
            int cq = tid + i * 256;
            int r = cq >> 3, c = cq & 7;
            const __half* g = Ab + (m0 + r) * lda + kt + c * 8;
            cp_async16(sa + r * 128 + ((c ^ (r & 7)) << 4), g);
        }
        uint32_t sb = sa + 16384;
        #pragma unroll
        for (int i = 0; i < 8; i++) {                       // B: 2048 chunks
            int cq = tid + i * 256;
            int r = cq >> 3, c = cq & 7;
            const __half* g = Bb + (long long)(n0 + r) * ldb + kt + c * 8;
            cp_async16(sb + r * 128 + ((c ^ (r & 7)) << 4), g);
        }
    };

    const int nK = K / 64;                                  // 64 for agg
    load_tile(0, 0); cp_commit();
    load_tile(1, 64); cp_commit();
    load_tile(2, 128); cp_commit();

    for (int tt = 0; tt < nK; tt++) {
        int rem = nK - 1 - tt;
        if (rem >= 2) cp_wait<2>(); else if (rem == 1) cp_wait<1>(); else cp_wait<0>();
        __syncthreads();
        if (tt + 3 < nK) { load_tile((tt + 3) & 3, (tt + 3) * 64); cp_commit(); }

        uint32_t sa = sbase + (tt & 3) * WSTAGE;
        uint32_t sb = sa + 16384;

        #pragma unroll
        for (int G = 0; G < 4; G++) {
            const int c0 = 2 * G;
            uint32_t a[4][4], bf[4][4];
            #pragma unroll
            for (int mi = 0; mi < 4; mi++) {
                int r = mW + mi * 16 + a_rl;
                int c = c0 + a_cs;
                ldsm_x4(a[mi], sa + r * 128 + ((c ^ (r & 7)) << 4));
            }
            #pragma unroll
            for (int nj = 0; nj < 4; nj++) {
                int n = nW + nj * 16 + b_nl;
                int c = c0 + b_cs;
                ldsm_x4(bf[nj], sb + n * 128 + ((c ^ (n & 7)) << 4));
            }
            #pragma unroll
            for (int mi = 0; mi < 4; mi++)
                #pragma unroll
                for (int ni = 0; ni < 8; ni++)
                    mma_f16(acc[mi][ni], a[mi], &bf[ni >> 1][(ni & 1) * 2]);
        }
    }
    __syncthreads();

    // ---------------- epilogue ----------------
    const __half* selfb = selfg + (long long)b * sSelfb;
    #pragma unroll
    for (int mi = 0; mi < 4; mi++) {
        #pragma unroll
        for (int rr = 0; rr < 2; rr++) {
            int m_loc = mW + mi * 16 + gr + rr * 8;
            long long m = m0 + m_loc;
            float d = ds[(long long)b * NNODE + m];
            #pragma unroll
            for (int ni = 0; ni < 8; ni++) {
                int col = n0 + nW + ni * 8 + 2 * t;
                float v0 = acc[mi][ni][rr * 2 + 0];
                float v1 = acc[mi][ni][rr * 2 + 1];
                float2 sv = __half22float2(*(const __half2*)(selfb + m * ldself + col));
                if (EPI == 0) {
                    v0 = d * (v0 + sv.x);
                    v1 = d * (v1 + sv.y);
                    int g16 = col >> 4, lp = (col >> 1) & 7;
                    __half* Ch = (__half*)Cg + (long long)b * sCb;
                    *(__half2*)(Ch + m * ldc + (g16 << 4) + (pos8(lp) << 1)) =
                        __floats2half2_rn(v0, v1);
                } else {  // EPI == 3
                    v0 = fmaf(d, v0 + sv.x, bias[col]);
                    v1 = fmaf(d, v1 + sv.y, bias[col + 1]);
                    float* Cf = (float*)Cg + (long long)b * sCb;
                    *(float2*)(Cf + m * ldc + col) = make_float2(v0, v1);
                }
            }
        }
    }
}

// ===========================================================================
// FUSED feature kernel: per CTA (128 rows):
//   H = relu(Z1_blk @ W1^T + b1) -> smem; P2 = ds∘(H @ W2^T); P2 + P2t out.
// 512 threads, occ 1, smem 224KB. Internal operands interleaved (lds64 path);
// P2t written PLAIN for the ldmatrix agg consumer.
// ===========================================================================
static constexpr int FZ1 = 0;               // Z1: 4 stages x 16KB = 64KB
static constexpr int FH  = 65536;           // H : 8 stages x 16KB = 128KB
static constexpr int FWB = 196608;          // W1 stream: 2 x 16KB
static constexpr int FW2 = 0;               // W2 stream: 2 x 32KB (reuses Z1)
static constexpr int FSMEM = 229376;        // 224 KB

__global__ void __launch_bounds__(512, 1) gemm_feat(
    const __half* __restrict__ Z1, const __half* __restrict__ W1t,
    const __half* __restrict__ W2t, const float* __restrict__ b1,
    const float* __restrict__ ds,
    __half* __restrict__ P2t, __half* __restrict__ P2) {

    extern __shared__ char smem[];
    const uint32_t sbase = smem_u32(smem);
    const int tid = threadIdx.x;
    const long long m0 = (long long)blockIdx.x * 128;

    const int warp = tid >> 5, lane = tid & 31;
    const int gr = lane >> 2, t = lane & 3;

    // ---- load Z1 block: 128 rows x 512B into 4 BK64 stages ----
    #pragma unroll
    for (int i = 0; i < 8; i++) {
        int q = tid + i * 512;            // 0..4095 16B-chunks
        int r = q >> 5, c = q & 31;
        const __half* g = Z1 + (m0 + r) * INC + c * 8;
        uint32_t st = c >> 3, cc = c & 7;
        cp_async16(sbase + FZ1 + st * 16384 + r * 128 + ((cc ^ (r & 7)) << 4), g);
    }
    cp_commit();

    // ================= GEMM1: H chunks of 128 hidden =================
    {
        const int mW = (warp >> 2) * 32, nW = (warp & 3) * 32;
        for (int hc = 0; hc < 4; hc++) {
            float acc[2][4][4];
            #pragma unroll
            for (int mi = 0; mi < 2; mi++)
                #pragma unroll
                for (int ni = 0; ni < 4; ni++)
                    #pragma unroll
                    for (int e = 0; e < 4; e++) acc[mi][ni][e] = 0.f;

            auto loadW1 = [&](int buf, int kk) {
                #pragma unroll
                for (int i = 0; i < 2; i++) {
                    int q = tid + i * 512;     // 0..1023 chunks (128 rows x 8)
                    int r = q >> 3, c = q & 7;
                    const __half* g = W1t + (size_t)(hc * 128 + r) * INC + kk * 64 + c * 8;
                    cp_async16(sbase + FWB + buf * 16384 + r * 128 + ((c ^ (r & 7)) << 4), g);
                }
            };
            loadW1(0, 0); cp_commit();

            for (int kk = 0; kk < 4; kk++) {
                if (kk + 1 < 4) { loadW1((kk + 1) & 1, kk + 1); cp_commit(); cp_wait<1>(); }
                else cp_wait<0>();
                __syncthreads();
                uint32_t sa = sbase + FZ1 + kk * 16384;
                uint32_t sb = sbase + FWB + (kk & 1) * 16384;
                #pragma unroll
                for (int G = 0; G < 4; G++) {
                    const int chunk = (G << 1) | (t >> 1);
                    const uint32_t swo = ((chunk ^ gr) << 4) + ((t & 1) << 3);
                    uint32_t a[2][4];
                    #pragma unroll
                    for (int mi = 0; mi < 2; mi++) {
                        uint32_t ra = sa + (mW + mi * 16 + gr) * 128 + swo;
                        lds64(a[mi][0], a[mi][2], ra);
                        lds64(a[mi][1], a[mi][3], ra + 1024);
                    }
                    #pragma unroll
                    for (int ni = 0; ni < 4; ni++) {
                        uint32_t bf[2];
                        lds64(bf[0], bf[1], sb + (nW + ni * 8 + gr) * 128 + swo);
                        #pragma unroll
                        for (int mi = 0; mi < 2; mi++)
                            mma_f16(acc[mi][ni], a[mi], bf);
                    }
                }
                __syncthreads();
            }

            // epilogue hc: relu+bias -> fp16 -> H operand stages (interleaved)
            #pragma unroll
            for (int mi = 0; mi < 2; mi++) {
                #pragma unroll
                for (int rr = 0; rr < 2; rr++) {
                    int m_loc = mW + mi * 16 + gr + rr * 8;
                    #pragma unroll
                    for (int ni = 0; ni < 4; ni++) {
                        int nl = nW + ni * 8 + 2 * t;
                        int h = hc * 128 + nl;
                        float2 bb = *(const float2*)(b1 + h);
                        float v0 = fmaxf(acc[mi][ni][rr * 2 + 0] + bb.x, 0.f);
                        float v1 = fmaxf(acc[mi][ni][rr * 2 + 1] + bb.y, 0.f);
                        __half2 hv = __floats2half2_rn(v0, v1);
                        int sH = h >> 6, k64 = h & 63;
                        int s = (k64 >> 4) * 16 + pos8((k64 >> 1) & 7) * 2;
                        int cch = s >> 3;
                        int win = (2 * s) & 15;
                        uint32_t addr = sbase + FH + sH * 16384 + m_loc * 128
                                      + ((cch ^ (m_loc & 7)) << 4) + win;
                        asm volatile("st.shared.b32 [%0], %1;"
                                     :: "r"(addr), "r"(*(uint32_t*)&hv));
                    }
                }
            }
        }
    }
    __syncthreads();   // H complete; Z1 region free for W2 buffers

    // ================= GEMM2: P2 = H @ W2^T (K=512) =================
    const int mW2 = (warp >> 2) * 32, nW2 = (warp & 3) * 64;
    float acc2[2][8][4];
    #pragma unroll
    for (int mi = 0; mi < 2; mi++)
        #pragma unroll
        for (int ni = 0; ni < 8; ni++)
            #pragma unroll
            for (int e = 0; e < 4; e++) acc2[mi][ni][e] = 0.f;

    auto loadW2 = [&](int buf, int kk) {
        #pragma unroll
        for (int i = 0; i < 4; i++) {
            int q = tid + i * 512;             // 0..2047 chunks (256 rows x 8)
            int r = q >> 3, c = q & 7;
            const __half* g = W2t + (size_t)r * HIDC + kk * 64 + c * 8;
            cp_async16(sbase + FW2 + buf * 32768 + r * 128 + ((c ^ (r & 7)) << 4), g);
        }
    };
    loadW2(0, 0); cp_commit();

    for (int kk = 0; kk < 8; kk++) {
        if (kk + 1 < 8) { loadW2((kk + 1) & 1, kk + 1); cp_commit(); cp_wait<1>(); }
        else cp_wait<0>();
        __syncthreads();
        uint32_t sa = sbase + FH + kk * 16384;
        uint32_t sb = sbase + FW2 + (kk & 1) * 32768;
        #pragma unroll
        for (int G = 0; G < 4; G++) {
            const int chunk = (G << 1) | (t >> 1);
            const uint32_t swo = ((chunk ^ gr) << 4) + ((t & 1) << 3);
            uint32_t a[2][4];
            #pragma unroll
            for (int mi = 0; mi < 2; mi++) {
                uint32_t ra = sa + (mW2 + mi * 16 + gr) * 128 + swo;
                lds64(a[mi][0], a[mi][2], ra);
                lds64(a[mi][1], a[mi][3], ra + 1024);
            }
            #pragma unroll
            for (int ni = 0; ni < 8; ni++) {
                uint32_t bf[2];
                lds64(bf[0], bf[1], sb + (nW2 + ni * 8 + gr) * 128 + swo);
                #pragma unroll
                for (int mi = 0; mi < 2; mi++)
                    mma_f16(acc2[mi][ni], a[mi], bf);
            }
        }
        __syncthreads();
    }

    // ---------------- epilogue: P2 plain + staged transpose for P2t (PLAIN) ----
    __half* sT = (__half*)(smem + FH);    // [256][136] halfs, reuses H region
    #pragma unroll
    for (int mi = 0; mi < 2; mi++) {
        #pragma unroll
        for (int rr = 0; rr < 2; rr++) {
            int m_loc = mW2 + mi * 16 + gr + rr * 8;
            long long m = m0 + m_loc;
            float d = ds[m];
            #pragma unroll
            for (int ni = 0; ni < 8; ni++) {
                int nl = nW2 + ni * 8 + 2 * t;
                float v0 = d * acc2[mi][ni][rr * 2 + 0];
                float v1 = d * acc2[mi][ni][rr * 2 + 1];
                __half2 hv = __floats2half2_rn(v0, v1);
                *(__half2*)(P2 + m * OUTC + nl) = hv;
                sT[nl * 136 + m_loc] = __low2half(hv);
                sT[(nl + 1) * 136 + m_loc] = __high2half(hv);
            }
        }
    }
    __syncthreads();

    // transposed PLAIN writeout: thread = (n, m-half)
    {
        int n = tid & 255, mh = tid >> 8;       // mh in {0,1}
        int b = (int)(m0 >> 12);
        long long m0loc = m0 & 4095;
        __half* Ct = P2t + (size_t)b * OUTC * NNODE + (size_t)n * NNODE + m0loc + mh * 64;
        #pragma unroll
        for (int mg = 0; mg < 4; mg++) {
            __half2 ph[8];
            #pragma unroll
            for (int pp = 0; pp < 8; pp++) {
                int mA = mh * 64 + mg * 16 + 2 * pp;
                ph[pp] = __halves2half2(sT[n * 136 + mA], sT[n * 136 + mA + 1]);
            }
            uint4* dst = (uint4*)(Ct + mg * 16);
            dst[0] = *(uint4*)&ph[0];
            dst[1] = *(uint4*)&ph[4];
        }
    }
}

// ---------------------------------------------------------------------------
// launch
// ---------------------------------------------------------------------------
extern "C" void kernel_launch(void* const* d_in, const int* in_sizes, int n_in,
                              void* d_out, int out_size) {
    const float* x  = (const float*)d_in[0];
    const float* A  = (const float*)d_in[1];
    const float* W1 = (const float*)d_in[2];
    const float* b1 = (const float*)d_in[3];
    const float* W2 = (const float*)d_in[4];
    const float* b2 = (const float*)d_in[5];
    float* out = (float*)d_out;

    float* ds;
    __half *Ar, *xs, *xst, *Z1, *P2t, *P2, *W1t, *W2t;
    cudaGetSymbolAddress((void**)&ds,  g_ds);
    cudaGetSymbolAddress((void**)&Ar,  g_Ar);
    cudaGetSymbolAddress((void**)&xs,  g_xs);
    cudaGetSymbolAddress((void**)&xst, g_xst);
    cudaGetSymbolAddress((void**)&Z1,  g_Z1);
    cudaGetSymbolAddress((void**)&P2t, g_P2t);
    cudaGetSymbolAddress((void**)&P2,  g_P2);
    cudaGetSymbolAddress((void**)&W1t, g_W1t);
    cudaGetSymbolAddress((void**)&W2t, g_W2t);

    cudaFuncSetAttribute(gemm_f16_wide<0>, cudaFuncAttributeMaxDynamicSharedMemorySize, WSMEM);
    cudaFuncSetAttribute(gemm_f16_wide<3>, cudaFuncAttributeMaxDynamicSharedMemorySize, WSMEM);
    cudaFuncSetAttribute(gemm_feat,        cudaFuncAttributeMaxDynamicSharedMemorySize, FSMEM);

    // prep
    prep_A_kernel<<<BATCH * NNODE, 256>>>(A, Ar, ds);
    prep_x_kernel<<<dim3(NNODE / 32, INC / 32, BATCH), 256>>>(x, ds, xs, xst);
    prep_W_both<<<512, 256>>>(W1, W2, W1t, W2t);

    // G1: Z1 = ds∘(A@xs + xs)   (wide agg, per-batch, N=256)
    gemm_f16_wide<0><<<dim3(INC / 256, NNODE / 128, BATCH), 256, WSMEM>>>(
        Ar, xst, Z1, xs, ds, nullptr,
        NNODE, NNODE, NNODE, INC, INC,
        (long long)NNODE * NNODE, (long long)INC * NNODE,
        (long long)NNODE * INC, (long long)NNODE * INC);

    // G2+G3 fused: H in smem, P2/P2t out
    gemm_feat<<<MT / 128, 512, FSMEM>>>(Z1, W1t, W2t, b1, ds, P2t, P2);

    // G4: out = ds∘(A@P2 + P2) + b2   (wide agg)
    gemm_f16_wide<3><<<dim3(OUTC / 256, NNODE / 128, BATCH), 256, WSMEM>>>(
        Ar, P2t, out, P2, ds, b2,
        NNODE, NNODE, NNODE, OUTC, OUTC,
        (long long)NNODE * NNODE, (long long)OUTC * NNODE,
        (long long)NNODE * OUTC, (long long)NNODE * OUTC);
}

// round 15
// speedup vs baseline: 1.2696x; 1.0237x over previous
#include <cuda_runtime.h>
#include <cuda_fp16.h>
#include <cstdint>

// ---------------------------------------------------------------------------
// GraphEncoder on GB300 (sm_103a) — fp16 mma.sync pipeline.
//
//   ds[i] = rsqrt(1 + rowsum(A)[i]);   xs = ds∘x  (fp16)
//   Z1  = ds∘(A@xs + xs)                     (agg, N=256)   [= nrm@x]
//   H   = relu(Z1@W1 + b1)                   (feature — smem only, fused)
//   P2  = ds∘(H@W2)                          (feature — fused kernel)
//   out = ds∘(A@P2 + P2) + b2                (agg, N=256)
//
// R14: ALL GEMMs on the ldmatrix path (plain K-order layouts everywhere —
// pos8 interleave fully removed). Agg adds explicit fragment double-buffering
// across G-steps. Fused feature kernel rebuilt on ldsm.
// ---------------------------------------------------------------------------

#define DEV_INLINE __device__ __forceinline__

static constexpr int BATCH = 8, NNODE = 4096, INC = 256, HIDC = 512, OUTC = 256;
static constexpr int MT = BATCH * NNODE;   // 32768

// Scratch (allocation-free __device__ globals)
__device__ float  g_ds [MT];
__device__ __half g_Ar [(size_t)BATCH * NNODE * NNODE];          // 256 MB plain
__device__ __half g_xs [(size_t)MT * INC];                       // plain
__device__ __half g_xst[(size_t)BATCH * INC * NNODE];            // T, plain
__device__ __half g_Z1 [(size_t)MT * INC];                       // plain
__device__ __half g_P2t[(size_t)BATCH * OUTC * NNODE];           // T, plain
__device__ __half g_P2 [(size_t)MT * OUTC];                      // plain
__device__ __half g_W1t[HIDC * INC];                             // plain K-major
__device__ __half g_W2t[OUTC * HIDC];                            // plain K-major

// ---------------------------------------------------------------------------
// helpers
// ---------------------------------------------------------------------------
DEV_INLINE void cp_async16(uint32_t saddr, const void* gmem) {
    asm volatile("cp.async.cg.shared.global [%0], [%1], 16;" :: "r"(saddr), "l"(gmem));
}
DEV_INLINE void cp_commit() { asm volatile("cp.async.commit_group;"); }
template <int N> DEV_INLINE void cp_wait() { asm volatile("cp.async.wait_group %0;" :: "n"(N)); }

DEV_INLINE uint32_t smem_u32(const void* p) {
    return (uint32_t)__cvta_generic_to_shared(p);
}

DEV_INLINE void ldsm_x4(uint32_t* r, uint32_t addr) {
    asm volatile("ldmatrix.sync.aligned.m8n8.x4.shared.b16 {%0,%1,%2,%3}, [%4];"
                 : "=r"(r[0]), "=r"(r[1]), "=r"(r[2]), "=r"(r[3]) : "r"(addr));
}

DEV_INLINE void mma_f16(float* d, const uint32_t* a, const uint32_t* b) {
    asm volatile(
        "mma.sync.aligned.m16n8k16.row.col.f32.f16.f16.f32 "
        "{%0,%1,%2,%3},{%4,%5,%6,%7},{%8,%9},{%0,%1,%2,%3};"
        : "+f"(d[0]), "+f"(d[1]), "+f"(d[2]), "+f"(d[3])
        : "r"(a[0]), "r"(a[1]), "r"(a[2]), "r"(a[3]), "r"(b[0]), "r"(b[1]));
}

// ---------------------------------------------------------------------------
// prep_A: ds[row] = rsqrt(1+rowsum), Ar = fp16(A) plain K-major
// ---------------------------------------------------------------------------
__global__ void __launch_bounds__(256) prep_A_kernel(const float* __restrict__ A,
                                                     __half* __restrict__ Ar,
                                                     float* __restrict__ ds) {
    __shared__ float srow[NNODE];
    long long row = blockIdx.x;
    const float4* p = (const float4*)(A + row * (long long)NNODE);
    float s = 0.f;
    #pragma unroll 2
    for (int i = threadIdx.x; i < NNODE / 4; i += 256) {
        float4 v = p[i];
        s += (v.x + v.y) + (v.z + v.w);
        *(float4*)(srow + 4 * i) = v;
    }
    #pragma unroll
    for (int o = 16; o; o >>= 1) s += __shfl_xor_sync(0xFFFFFFFFu, s, o);
    __shared__ float ws[8];
    if ((threadIdx.x & 31) == 0) ws[threadIdx.x >> 5] = s;
    __syncthreads();
    if (threadIdx.x == 0) {
        float tot = 0.f;
        #pragma unroll
        for (int i = 0; i < 8; i++) tot += ws[i];
        ds[row] = rsqrtf(tot + 1.0f);
    }
    int g = threadIdx.x;
    const float* src = srow + 16 * g;
    __half2 ph[8];
    #pragma unroll
    for (int pp = 0; pp < 8; pp++)
        ph[pp] = __floats2half2_rn(src[2 * pp], src[2 * pp + 1]);
    uint4* dst = (uint4*)(Ar + row * (long long)NNODE + 16 * g);
    dst[0] = *(uint4*)&ph[0];
    dst[1] = *(uint4*)&ph[4];
}

// ---------------------------------------------------------------------------
// prep_x: xs = fp16(ds∘x) plain row-major; xst = transposed plain
// ---------------------------------------------------------------------------
__global__ void __launch_bounds__(256) prep_x_kernel(const float* __restrict__ x,
                                                     const float* __restrict__ ds,
                                                     __half* __restrict__ xs,
                                                     __half* __restrict__ xst) {
    __shared__ __half sm[32][34];
    int m0 = blockIdx.x * 32, c0 = blockIdx.y * 32, b = blockIdx.z;
    #pragma unroll
    for (int r4 = 0; r4 < 4; r4++) {
        int idx = threadIdx.x + r4 * 256;
        int im = idx >> 5, ic = idx & 31;
        long long gm = (long long)b * NNODE + m0 + im;
        float v = x[gm * INC + c0 + ic] * ds[gm];
        __half h = __float2half_rn(v);
        sm[im][ic] = h;
        xs[gm * INC + c0 + ic] = h;
    }
    __syncthreads();
    #pragma unroll
    for (int r2 = 0; r2 < 2; r2++) {
        int pidx = threadIdx.x + r2 * 256;
        int jc = pidx >> 4, lp = pidx & 15;
        int mA = 2 * lp;
        __half2 hv = __halves2half2(sm[mA][jc], sm[mA + 1][jc]);
        long long dst = (long long)b * INC * NNODE + (long long)(c0 + jc) * NNODE
                      + m0 + mA;
        *(__half2*)(xst + dst) = hv;
    }
}

// ---------------------------------------------------------------------------
// prep_W_both: plain transposes (one launch)
// ---------------------------------------------------------------------------
__global__ void __launch_bounds__(256) prep_W_both(const float* __restrict__ W1,
                                                   const float* __restrict__ W2,
                                                   __half* __restrict__ W1t,
                                                   __half* __restrict__ W2t) {
    int blk = blockIdx.x;
    const float* W; __half* Wt; int K, N, id;
    if (blk < 256) { W = W1; Wt = W1t; K = INC;  N = HIDC; id = blk * 256 + threadIdx.x; }
    else           { W = W2; Wt = W2t; K = HIDC; N = OUTC; id = (blk - 256) * 256 + threadIdx.x; }
    if (id >= N * (K / 2)) return;
    int n = id / (K / 2), pk = id % (K / 2);
    int k = 2 * pk;
    __half2 hv = __floats2half2_rn(W[(long long)k * N + n], W[(long long)(k + 1) * N + n]);
    *(__half2*)(Wt + (long long)n * K + k) = hv;
}

// ===========================================================================
// WIDE agg GEMM (ldsm + fragment double-buffer): CTA 128x256, 256 threads =
// 8 warps (2x4) of 64x64, BK=64, 4-stage ring (192KB), occ 1.
//   EPI 0: Z1[m][n] = ds[m]*(acc + self[m][n])      -> half plain
//   EPI 3: out[m][n] = ds[m]*(acc + self[m][n]) + bias[n]  -> fp32
// ===========================================================================
static constexpr int WSTAGE = 49152;                 // A 16KB + B 32KB
static constexpr int WSMEM  = 4 * WSTAGE;            // 192 KB

template <int EPI>
__global__ void __launch_bounds__(256, 1) gemm_f16_wide(
    const __half* __restrict__ Ag, const __half* __restrict__ Bg, void* __restrict__ Cg,
    const __half* __restrict__ selfg, const float* __restrict__ ds,
    const float* __restrict__ bias,
    int K, long long lda, long long ldb, long long ldc, long long ldself,
    long long sAb, long long sBb, long long sCb, long long sSelfb) {

    extern __shared__ char smem[];
    const uint32_t sbase = smem_u32(smem);

    const int tid = threadIdx.x;
    const int b = blockIdx.z;
    const long long m0 = (long long)blockIdx.y * 128;
    const int n0 = blockIdx.x * 256;

    const __half* Ab = Ag + (long long)b * sAb;
    const __half* Bb = Bg + (long long)b * sBb;

    const int warp = tid >> 5, lane = tid & 31;
    const int gr = lane >> 2, t = lane & 3;
    const int mW = (warp >> 2) * 64, nW = (warp & 3) * 64;

    const int a_rl = lane & 15;
    const int a_cs = lane >> 4;
    const int b_nl = ((lane >> 4) << 3) + (lane & 7);
    const int b_cs = (lane >> 3) & 1;

    float acc[4][8][4];
    #pragma unroll
    for (int mi = 0; mi < 4; mi++)
        #pragma unroll
        for (int ni = 0; ni < 8; ni++)
            #pragma unroll
            for (int e = 0; e < 4; e++) acc[mi][ni][e] = 0.f;

    auto load_tile = [&](int st, int kt) {
        uint32_t sa = sbase + st * WSTAGE;
        #pragma unroll
        for (int i = 0; i < 4; i++) {
            int cq = tid + i * 256;
            int r = cq >> 3, c = cq & 7;
            const __half* g = Ab + (m0 + r) * lda + kt + c * 8;
            cp_async16(sa + r * 128 + ((c ^ (r & 7)) << 4), g);
        }
        uint32_t sb = sa + 16384;
        #pragma unroll
        for (int i = 0; i < 8; i++) {
            int cq = tid + i * 256;
            int r = cq >> 3, c = cq & 7;
            const __half* g = Bb + (long long)(n0 + r) * ldb + kt + c * 8;
            cp_async16(sb + r * 128 + ((c ^ (r & 7)) << 4), g);
        }
    };

    uint32_t afr[2][4][4], bfr[2][4][4];
    auto ld_frags = [&](int buf, uint32_t sa, uint32_t sb, int G) {
        const int c0 = 2 * G;
        #pragma unroll
        for (int mi = 0; mi < 4; mi++) {
            int r = mW + mi * 16 + a_rl;
            int c = c0 + a_cs;
            ldsm_x4(afr[buf][mi], sa + r * 128 + ((c ^ (r & 7)) << 4));
        }
        #pragma unroll
        for (int nj = 0; nj < 4; nj++) {
            int n = nW + nj * 16 + b_nl;
            int c = c0 + b_cs;
            ldsm_x4(bfr[buf][nj], sb + n * 128 + ((c ^ (n & 7)) << 4));
        }
    };

    const int nK = K / 64;
    load_tile(0, 0); cp_commit();
    load_tile(1, 64); cp_commit();
    load_tile(2, 128); cp_commit();

    for (int tt = 0; tt < nK; tt++) {
        int rem = nK - 1 - tt;
        if (rem >= 2) cp_wait<2>(); else if (rem == 1) cp_wait<1>(); else cp_wait<0>();
        __syncthreads();
        if (tt + 3 < nK) { load_tile((tt + 3) & 3, (tt + 3) * 64); cp_commit(); }

        uint32_t sa = sbase + (tt & 3) * WSTAGE;
        uint32_t sb = sa + 16384;

        ld_frags(0, sa, sb, 0);
        #pragma unroll
        for (int G = 0; G < 4; G++) {
            if (G < 3) ld_frags((G + 1) & 1, sa, sb, G + 1);
            const int cur = G & 1;
            #pragma unroll
            for (int mi = 0; mi < 4; mi++)
                #pragma unroll
                for (int ni = 0; ni < 8; ni++)
                    mma_f16(acc[mi][ni], afr[cur][mi], &bfr[cur][ni >> 1][(ni & 1) * 2]);
        }
    }
    __syncthreads();

    // ---------------- epilogue ----------------
    const __half* selfb = selfg + (long long)b * sSelfb;
    #pragma unroll
    for (int mi = 0; mi < 4; mi++) {
        #pragma unroll
        for (int rr = 0; rr < 2; rr++) {
            int m_loc = mW + mi * 16 + gr + rr * 8;
            long long m = m0 + m_loc;
            float d = ds[(long long)b * NNODE + m];
            #pragma unroll
            for (int ni = 0; ni < 8; ni++) {
                int col = n0 + nW + ni * 8 + 2 * t;
                float v0 = acc[mi][ni][rr * 2 + 0];
                float v1 = acc[mi][ni][rr * 2 + 1];
                float2 sv = __half22float2(*(const __half2*)(selfb + m * ldself + col));
                if (EPI == 0) {
                    v0 = d * (v0 + sv.x);
                    v1 = d * (v1 + sv.y);
                    __half* Ch = (__half*)Cg + (long long)b * sCb;
                    *(__half2*)(Ch + m * ldc + col) = __floats2half2_rn(v0, v1);
                } else {  // EPI == 3
                    v0 = fmaf(d, v0 + sv.x, bias[col]);
                    v1 = fmaf(d, v1 + sv.y, bias[col + 1]);
                    float* Cf = (float*)Cg + (long long)b * sCb;
                    *(float2*)(Cf + m * ldc + col) = make_float2(v0, v1);
                }
            }
        }
    }
}

// ===========================================================================
// FUSED feature kernel (ldsm path): per CTA (128 rows):
//   H = relu(Z1_blk @ W1^T + b1) -> smem (plain+swizzle); P2 = ds∘(H @ W2^T);
//   P2 plain + P2t transposed-plain out. 512 threads, occ 1, smem 224KB.
// ===========================================================================
static constexpr int FZ1 = 0;               // Z1: 4 stages x 16KB = 64KB
static constexpr int FH  = 65536;           // H : 8 stages x 16KB = 128KB
static constexpr int FWB = 196608;          // W1 stream: 2 x 16KB
static constexpr int FW2 = 0;               // W2 stream: 2 x 32KB (reuses Z1)
static constexpr int FSMEM = 229376;        // 224 KB

__global__ void __launch_bounds__(512, 1) gemm_feat(
    const __half* __restrict__ Z1, const __half* __restrict__ W1t,
    const __half* __restrict__ W2t, const float* __restrict__ b1,
    const float* __restrict__ ds,
    __half* __restrict__ P2t, __half* __restrict__ P2) {

    extern __shared__ char smem[];
    const uint32_t sbase = smem_u32(smem);
    const int tid = threadIdx.x;
    const long long m0 = (long long)blockIdx.x * 128;

    const int warp = tid >> 5, lane = tid & 31;
    const int gr = lane >> 2, t = lane & 3;

    const int a_rl = lane & 15;
    const int a_cs = lane >> 4;
    const int b_nl = ((lane >> 4) << 3) + (lane & 7);
    const int b_cs = (lane >> 3) & 1;

    // ---- load Z1 block: 128 rows x 512B into 4 BK64 stages ----
    #pragma unroll
    for (int i = 0; i < 8; i++) {
        int q = tid + i * 512;
        int r = q >> 5, c = q & 31;
        const __half* g = Z1 + (m0 + r) * INC + c * 8;
        uint32_t st = c >> 3, cc = c & 7;
        cp_async16(sbase + FZ1 + st * 16384 + r * 128 + ((cc ^ (r & 7)) << 4), g);
    }
    cp_commit();

    // ================= GEMM1: H chunks of 128 hidden =================
    {
        const int mW = (warp >> 2) * 32, nW = (warp & 3) * 32;
        for (int hc = 0; hc < 4; hc++) {
            float acc[2][4][4];
            #pragma unroll
            for (int mi = 0; mi < 2; mi++)
                #pragma unroll
                for (int ni = 0; ni < 4; ni++)
                    #pragma unroll
                    for (int e = 0; e < 4; e++) acc[mi][ni][e] = 0.f;

            auto loadW1 = [&](int buf, int kk) {
                #pragma unroll
                for (int i = 0; i < 2; i++) {
                    int q = tid + i * 512;
                    int r = q >> 3, c = q & 7;
                    const __half* g = W1t + (size_t)(hc * 128 + r) * INC + kk * 64 + c * 8;
                    cp_async16(sbase + FWB + buf * 16384 + r * 128 + ((c ^ (r & 7)) << 4), g);
                }
            };
            loadW1(0, 0); cp_commit();

            for (int kk = 0; kk < 4; kk++) {
                if (kk + 1 < 4) { loadW1((kk + 1) & 1, kk + 1); cp_commit(); cp_wait<1>(); }
                else cp_wait<0>();
                __syncthreads();
                uint32_t sa = sbase + FZ1 + kk * 16384;
                uint32_t sb = sbase + FWB + (kk & 1) * 16384;
                #pragma unroll
                for (int G = 0; G < 4; G++) {
                    const int c0 = 2 * G;
                    uint32_t a[2][4], bf[2][4];
                    #pragma unroll
                    for (int mi = 0; mi < 2; mi++) {
                        int r = mW + mi * 16 + a_rl;
                        int c = c0 + a_cs;
                        ldsm_x4(a[mi], sa + r * 128 + ((c ^ (r & 7)) << 4));
                    }
                    #pragma unroll
                    for (int nj = 0; nj < 2; nj++) {
                        int n = nW + nj * 16 + b_nl;
                        int c = c0 + b_cs;
                        ldsm_x4(bf[nj], sb + n * 128 + ((c ^ (n & 7)) << 4));
                    }
                    #pragma unroll
                    for (int mi = 0; mi < 2; mi++)
                        #pragma unroll
                        for (int ni = 0; ni < 4; ni++)
                            mma_f16(acc[mi][ni], a[mi], &bf[ni >> 1][(ni & 1) * 2]);
                }
                __syncthreads();
            }

            // epilogue hc: relu+bias -> fp16 -> H stages (plain + swizzle)
            #pragma unroll
            for (int mi = 0; mi < 2; mi++) {
                #pragma unroll
                for (int rr = 0; rr < 2; rr++) {
                    int m_loc = mW + mi * 16 + gr + rr * 8;
                    #pragma unroll
                    for (int ni = 0; ni < 4; ni++) {
                        int nl = nW + ni * 8 + 2 * t;
                        int h = hc * 128 + nl;
                        float2 bb = *(const float2*)(b1 + h);
                        float v0 = fmaxf(acc[mi][ni][rr * 2 + 0] + bb.x, 0.f);
                        float v1 = fmaxf(acc[mi][ni][rr * 2 + 1] + bb.y, 0.f);
                        __half2 hv = __floats2half2_rn(v0, v1);
                        int sH = h >> 6, k64 = h & 63;
                        int cch = k64 >> 3;
                        uint32_t addr = sbase + FH + sH * 16384 + m_loc * 128
                                      + ((cch ^ (m_loc & 7)) << 4) + (k64 & 7) * 2;
                        asm volatile("st.shared.b32 [%0], %1;"
                                     :: "r"(addr), "r"(*(uint32_t*)&hv));
                    }
                }
            }
        }
    }
    __syncthreads();   // H complete; Z1 region free for W2 buffers

    // ================= GEMM2: P2 = H @ W2^T (K=512) =================
    const int mW2 = (warp >> 2) * 32, nW2 = (warp & 3) * 64;
    float acc2[2][8][4];
    #pragma unroll
    for (int mi = 0; mi < 2; mi++)
        #pragma unroll
        for (int ni = 0; ni < 8; ni++)
            #pragma unroll
            for (int e = 0; e < 4; e++) acc2[mi][ni][e] = 0.f;

    auto loadW2 = [&](int buf, int kk) {
        #pragma unroll
        for (int i = 0; i < 4; i++) {
            int q = tid + i * 512;
            int r = q >> 3, c = q & 7;
            const __half* g = W2t + (size_t)r * HIDC + kk * 64 + c * 8;
            cp_async16(sbase + FW2 + buf * 32768 + r * 128 + ((c ^ (r & 7)) << 4), g);
        }
    };
    loadW2(0, 0); cp_commit();

    for (int kk = 0; kk < 8; kk++) {
        if (kk + 1 < 8) { loadW2((kk + 1) & 1, kk + 1); cp_commit(); cp_wait<1>(); }
        else cp_wait<0>();
        __syncthreads();
        uint32_t sa = sbase + FH + kk * 16384;
        uint32_t sb = sbase + FW2 + (kk & 1) * 32768;
        #pragma unroll
        for (int G = 0; G < 4; G++) {
            const int c0 = 2 * G;
            uint32_t a[2][4], bf[4][4];
            #pragma unroll
            for (int mi = 0; mi < 2; mi++) {
                int r = mW2 + mi * 16 + a_rl;
                int c = c0 + a_cs;
                ldsm_x4(a[mi], sa + r * 128 + ((c ^ (r & 7)) << 4));
            }
            #pragma unroll
            for (int nj = 0; nj < 4; nj++) {
                int n = nW2 + nj * 16 + b_nl;
                int c = c0 + b_cs;
                ldsm_x4(bf[nj], sb + n * 128 + ((c ^ (n & 7)) << 4));
            }
            #pragma unroll
            for (int mi = 0; mi < 2; mi++)
                #pragma unroll
                for (int ni = 0; ni < 8; ni++)
                    mma_f16(acc2[mi][ni], a[mi], &bf[ni >> 1][(ni & 1) * 2]);
        }
        __syncthreads();
    }

    // ---------------- epilogue: P2 plain + staged transpose for P2t ----------
    __half* sT = (__half*)(smem + FH);    // [256][136] halfs, reuses H region
    #pragma unroll
    for (int mi = 0; mi < 2; mi++) {
        #pragma unroll
        for (int rr = 0; rr < 2; rr++) {
            int m_loc = mW2 + mi * 16 + gr + rr * 8;
            long long m = m0 + m_loc;
            float d = ds[m];
            #pragma unroll
            for (int ni = 0; ni < 8; ni++) {
                int nl = nW2 + ni * 8 + 2 * t;
                float v0 = d * acc2[mi][ni][rr * 2 + 0];
                float v1 = d * acc2[mi][ni][rr * 2 + 1];
                __half2 hv = __floats2half2_rn(v0, v1);
                *(__half2*)(P2 + m * OUTC + nl) = hv;
                sT[nl * 136 + m_loc] = __low2half(hv);
                sT[(nl + 1) * 136 + m_loc] = __high2half(hv);
            }
        }
    }
    __syncthreads();

    // transposed plain writeout: thread = (n, m-half)
    {
        int n = tid & 255, mh = tid >> 8;
        int b = (int)(m0 >> 12);
        long long m0loc = m0 & 4095;
        __half* Ct = P2t + (size_t)b * OUTC * NNODE + (size_t)n * NNODE + m0loc + mh * 64;
        #pragma unroll
        for (int mg = 0; mg < 4; mg++) {
            __half2 ph[8];
            #pragma unroll
            for (int pp = 0; pp < 8; pp++) {
                int mA = mh * 64 + mg * 16 + 2 * pp;
                ph[pp] = __halves2half2(sT[n * 136 + mA], sT[n * 136 + mA + 1]);
            }
            uint4* dst = (uint4*)(Ct + mg * 16);
            dst[0] = *(uint4*)&ph[0];
            dst[1] = *(uint4*)&ph[4];
        }
    }
}

// ---------------------------------------------------------------------------
// launch
// ---------------------------------------------------------------------------
extern "C" void kernel_launch(void* const* d_in, const int* in_sizes, int n_in,
                              void* d_out, int out_size) {
    const float* x  = (const float*)d_in[0];
    const float* A  = (const float*)d_in[1];
    const float* W1 = (const float*)d_in[2];
    const float* b1 = (const float*)d_in[3];
    const float* W2 = (const float*)d_in[4];
    const float* b2 = (const float*)d_in[5];
    float* out = (float*)d_out;

    float* ds;
    __half *Ar, *xs, *xst, *Z1, *P2t, *P2, *W1t, *W2t;
    cudaGetSymbolAddress((void**)&ds,  g_ds);
    cudaGetSymbolAddress((void**)&Ar,  g_Ar);
    cudaGetSymbolAddress((void**)&xs,  g_xs);
    cudaGetSymbolAddress((void**)&xst, g_xst);
    cudaGetSymbolAddress((void**)&Z1,  g_Z1);
    cudaGetSymbolAddress((void**)&P2t, g_P2t);
    cudaGetSymbolAddress((void**)&P2,  g_P2);
    cudaGetSymbolAddress((void**)&W1t, g_W1t);
    cudaGetSymbolAddress((void**)&W2t, g_W2t);

    cudaFuncSetAttribute(gemm_f16_wide<0>, cudaFuncAttributeMaxDynamicSharedMemorySize, WSMEM);
    cudaFuncSetAttribute(gemm_f16_wide<3>, cudaFuncAttributeMaxDynamicSharedMemorySize, WSMEM);
    cudaFuncSetAttribute(gemm_feat,        cudaFuncAttributeMaxDynamicSharedMemorySize, FSMEM);

    // prep
    prep_A_kernel<<<BATCH * NNODE, 256>>>(A, Ar, ds);
    prep_x_kernel<<<dim3(NNODE / 32, INC / 32, BATCH), 256>>>(x, ds, xs, xst);
    prep_W_both<<<512, 256>>>(W1, W2, W1t, W2t);

    // G1: Z1 = ds∘(A@xs + xs)
    gemm_f16_wide<0><<<dim3(INC / 256, NNODE / 128, BATCH), 256, WSMEM>>>(
        Ar, xst, Z1, xs, ds, nullptr,
        NNODE, NNODE, NNODE, INC, INC,
        (long long)NNODE * NNODE, (long long)INC * NNODE,
        (long long)NNODE * INC, (long long)NNODE * INC);

    // G2+G3 fused
    gemm_feat<<<MT / 128, 512, FSMEM>>>(Z1, W1t, W2t, b1, ds, P2t, P2);

    // G4: out = ds∘(A@P2 + P2) + b2
    gemm_f16_wide<3><<<dim3(OUTC / 256, NNODE / 128, BATCH), 256, WSMEM>>>(
        Ar, P2t, out, P2, ds, b2,
        NNODE, NNODE, NNODE, OUTC, OUTC,
        (long long)NNODE * NNODE, (long long)OUTC * NNODE,
        (long long)NNODE * OUTC, (long long)NNODE * OUTC);
}

// round 16
// speedup vs baseline: 1.3065x; 1.0291x over previous
#include <cuda_runtime.h>
#include <cuda_fp16.h>
#include <cstdint>

// ---------------------------------------------------------------------------
// GraphEncoder on GB300 (sm_103a) — fp16 mma.sync pipeline.
//
//   ds[i] = rsqrt(1 + rowsum(A)[i]);   xs = ds∘x  (fp16)
//   Z1  = ds∘(A@xs + xs)                     (agg, N=256)   [= nrm@x]
//   H   = relu(Z1@W1 + b1)                   (feature — smem only, fused)
//   P2  = ds∘(H@W2)                          (feature — fused kernel)
//   out = ds∘(A@P2 + P2) + b2                (agg, N=256)
//
// R15: agg per-iter __syncthreads replaced by split named-barrier pipeline
// (data bar from iter t-2, overwrite bar from iter t-1) to absorb warp skew.
// Fused feature kernel: GEMM1 rebalanced to 32x64 warp tiles (Z1 ring 2x16KB,
// W ring 2x32KB, H 128KB = 224KB smem).
// ---------------------------------------------------------------------------

#define DEV_INLINE __device__ __forceinline__

static constexpr int BATCH = 8, NNODE = 4096, INC = 256, HIDC = 512, OUTC = 256;
static constexpr int MT = BATCH * NNODE;   // 32768

// Scratch (allocation-free __device__ globals)
__device__ float  g_ds [MT];
__device__ __half g_Ar [(size_t)BATCH * NNODE * NNODE];          // 256 MB plain
__device__ __half g_xs [(size_t)MT * INC];                       // plain
__device__ __half g_xst[(size_t)BATCH * INC * NNODE];            // T, plain
__device__ __half g_Z1 [(size_t)MT * INC];                       // plain
__device__ __half g_P2t[(size_t)BATCH * OUTC * NNODE];           // T, plain
__device__ __half g_P2 [(size_t)MT * OUTC];                      // plain
__device__ __half g_W1t[HIDC * INC];                             // plain K-major
__device__ __half g_W2t[OUTC * HIDC];                            // plain K-major

// ---------------------------------------------------------------------------
// helpers
// ---------------------------------------------------------------------------
DEV_INLINE void cp_async16(uint32_t saddr, const void* gmem) {
    asm volatile("cp.async.cg.shared.global [%0], [%1], 16;" :: "r"(saddr), "l"(gmem));
}
DEV_INLINE void cp_commit() { asm volatile("cp.async.commit_group;"); }
template <int N> DEV_INLINE void cp_wait() { asm volatile("cp.async.wait_group %0;" :: "n"(N)); }

DEV_INLINE uint32_t smem_u32(const void* p) {
    return (uint32_t)__cvta_generic_to_shared(p);
}

DEV_INLINE void ldsm_x4(uint32_t* r, uint32_t addr) {
    asm volatile("ldmatrix.sync.aligned.m8n8.x4.shared.b16 {%0,%1,%2,%3}, [%4];"
                 : "=r"(r[0]), "=r"(r[1]), "=r"(r[2]), "=r"(r[3]) : "r"(addr));
}

DEV_INLINE void mma_f16(float* d, const uint32_t* a, const uint32_t* b) {
    asm volatile(
        "mma.sync.aligned.m16n8k16.row.col.f32.f16.f16.f32 "
        "{%0,%1,%2,%3},{%4,%5,%6,%7},{%8,%9},{%0,%1,%2,%3};"
        : "+f"(d[0]), "+f"(d[1]), "+f"(d[2]), "+f"(d[3])
        : "r"(a[0]), "r"(a[1]), "r"(a[2]), "r"(a[3]), "r"(b[0]), "r"(b[1]));
}

DEV_INLINE void bar_sync_id(int id, int cnt) {
    asm volatile("bar.sync %0, %1;" :: "r"(id), "r"(cnt) : "memory");
}
DEV_INLINE void bar_arrive_id(int id, int cnt) {
    asm volatile("bar.arrive %0, %1;" :: "r"(id), "r"(cnt) : "memory");
}

// ---------------------------------------------------------------------------
// prep_A: ds[row] = rsqrt(1+rowsum), Ar = fp16(A) plain K-major
// ---------------------------------------------------------------------------
__global__ void __launch_bounds__(256) prep_A_kernel(const float* __restrict__ A,
                                                     __half* __restrict__ Ar,
                                                     float* __restrict__ ds) {
    __shared__ float srow[NNODE];
    long long row = blockIdx.x;
    const float4* p = (const float4*)(A + row * (long long)NNODE);
    float s = 0.f;
    #pragma unroll 2
    for (int i = threadIdx.x; i < NNODE / 4; i += 256) {
        float4 v = p[i];
        s += (v.x + v.y) + (v.z + v.w);
        *(float4*)(srow + 4 * i) = v;
    }
    #pragma unroll
    for (int o = 16; o; o >>= 1) s += __shfl_xor_sync(0xFFFFFFFFu, s, o);
    __shared__ float ws[8];
    if ((threadIdx.x & 31) == 0) ws[threadIdx.x >> 5] = s;
    __syncthreads();
    if (threadIdx.x == 0) {
        float tot = 0.f;
        #pragma unroll
        for (int i = 0; i < 8; i++) tot += ws[i];
        ds[row] = rsqrtf(tot + 1.0f);
    }
    int g = threadIdx.x;
    const float* src = srow + 16 * g;
    __half2 ph[8];
    #pragma unroll
    for (int pp = 0; pp < 8; pp++)
        ph[pp] = __floats2half2_rn(src[2 * pp], src[2 * pp + 1]);
    uint4* dst = (uint4*)(Ar + row * (long long)NNODE + 16 * g);
    dst[0] = *(uint4*)&ph[0];
    dst[1] = *(uint4*)&ph[4];
}

// ---------------------------------------------------------------------------
// prep_x: xs = fp16(ds∘x) plain row-major; xst = transposed plain
// ---------------------------------------------------------------------------
__global__ void __launch_bounds__(256) prep_x_kernel(const float* __restrict__ x,
                                                     const float* __restrict__ ds,
                                                     __half* __restrict__ xs,
                                                     __half* __restrict__ xst) {
    __shared__ __half sm[32][34];
    int m0 = blockIdx.x * 32, c0 = blockIdx.y * 32, b = blockIdx.z;
    #pragma unroll
    for (int r4 = 0; r4 < 4; r4++) {
        int idx = threadIdx.x + r4 * 256;
        int im = idx >> 5, ic = idx & 31;
        long long gm = (long long)b * NNODE + m0 + im;
        float v = x[gm * INC + c0 + ic] * ds[gm];
        __half h = __float2half_rn(v);
        sm[im][ic] = h;
        xs[gm * INC + c0 + ic] = h;
    }
    __syncthreads();
    #pragma unroll
    for (int r2 = 0; r2 < 2; r2++) {
        int pidx = threadIdx.x + r2 * 256;
        int jc = pidx >> 4, lp = pidx & 15;
        int mA = 2 * lp;
        __half2 hv = __halves2half2(sm[mA][jc], sm[mA + 1][jc]);
        long long dst = (long long)b * INC * NNODE + (long long)(c0 + jc) * NNODE
                      + m0 + mA;
        *(__half2*)(xst + dst) = hv;
    }
}

// ---------------------------------------------------------------------------
// prep_W_both: plain transposes (one launch)
// ---------------------------------------------------------------------------
__global__ void __launch_bounds__(256) prep_W_both(const float* __restrict__ W1,
                                                   const float* __restrict__ W2,
                                                   __half* __restrict__ W1t,
                                                   __half* __restrict__ W2t) {
    int blk = blockIdx.x;
    const float* W; __half* Wt; int K, N, id;
    if (blk < 256) { W = W1; Wt = W1t; K = INC;  N = HIDC; id = blk * 256 + threadIdx.x; }
    else           { W = W2; Wt = W2t; K = HIDC; N = OUTC; id = (blk - 256) * 256 + threadIdx.x; }
    if (id >= N * (K / 2)) return;
    int n = id / (K / 2), pk = id % (K / 2);
    int k = 2 * pk;
    __half2 hv = __floats2half2_rn(W[(long long)k * N + n], W[(long long)(k + 1) * N + n]);
    *(__half2*)(Wt + (long long)n * K + k) = hv;
}

// ===========================================================================
// WIDE agg GEMM (ldsm + named-barrier pipeline): CTA 128x256, 256 threads =
// 8 warps (2x4) of 64x64, BK=64, 4-stage ring (192KB), occ 1.
// Sync: data bar (ids 1-4) certifies all warps' cp groups <= t (from iter t-2);
// overwrite bar (ids 5-8) certifies compute(t-1) done before loads of t+3.
//   EPI 0: Z1[m][n] = ds[m]*(acc + self[m][n])      -> half plain
//   EPI 3: out[m][n] = ds[m]*(acc + self[m][n]) + bias[n]  -> fp32
// ===========================================================================
static constexpr int WSTAGE = 49152;                 // A 16KB + B 32KB
static constexpr int WSMEM  = 4 * WSTAGE;            // 192 KB

template <int EPI>
__global__ void __launch_bounds__(256, 1) gemm_f16_wide(
    const __half* __restrict__ Ag, const __half* __restrict__ Bg, void* __restrict__ Cg,
    const __half* __restrict__ selfg, const float* __restrict__ ds,
    const float* __restrict__ bias,
    int K, long long lda, long long ldb, long long ldc, long long ldself,
    long long sAb, long long sBb, long long sCb, long long sSelfb) {

    extern __shared__ char smem[];
    const uint32_t sbase = smem_u32(smem);

    const int tid = threadIdx.x;
    const int b = blockIdx.z;
    const long long m0 = (long long)blockIdx.y * 128;
    const int n0 = blockIdx.x * 256;

    const __half* Ab = Ag + (long long)b * sAb;
    const __half* Bb = Bg + (long long)b * sBb;

    const int warp = tid >> 5, lane = tid & 31;
    const int gr = lane >> 2, t = lane & 3;
    const int mW = (warp >> 2) * 64, nW = (warp & 3) * 64;

    const int a_rl = lane & 15;
    const int a_cs = lane >> 4;
    const int b_nl = ((lane >> 4) << 3) + (lane & 7);
    const int b_cs = (lane >> 3) & 1;

    float acc[4][8][4];
    #pragma unroll
    for (int mi = 0; mi < 4; mi++)
        #pragma unroll
        for (int ni = 0; ni < 8; ni++)
            #pragma unroll
            for (int e = 0; e < 4; e++) acc[mi][ni][e] = 0.f;

    auto load_tile = [&](int st, int kt) {
        uint32_t sa = sbase + st * WSTAGE;
        #pragma unroll
        for (int i = 0; i < 4; i++) {
            int cq = tid + i * 256;
            int r = cq >> 3, c = cq & 7;
            const __half* g = Ab + (m0 + r) * lda + kt + c * 8;
            cp_async16(sa + r * 128 + ((c ^ (r & 7)) << 4), g);
        }
        uint32_t sb = sa + 16384;
        #pragma unroll
        for (int i = 0; i < 8; i++) {
            int cq = tid + i * 256;
            int r = cq >> 3, c = cq & 7;
            const __half* g = Bb + (long long)(n0 + r) * ldb + kt + c * 8;
            cp_async16(sb + r * 128 + ((c ^ (r & 7)) << 4), g);
        }
    };

    uint32_t afr[2][4][4], bfr[2][4][4];
    auto ld_frags = [&](int buf, uint32_t sa, uint32_t sb, int G) {
        const int c0 = 2 * G;
        #pragma unroll
        for (int mi = 0; mi < 4; mi++) {
            int r = mW + mi * 16 + a_rl;
            int c = c0 + a_cs;
            ldsm_x4(afr[buf][mi], sa + r * 128 + ((c ^ (r & 7)) << 4));
        }
        #pragma unroll
        for (int nj = 0; nj < 4; nj++) {
            int n = nW + nj * 16 + b_nl;
            int c = c0 + b_cs;
            ldsm_x4(bfr[buf][nj], sb + n * 128 + ((c ^ (n & 7)) << 4));
        }
    };

    const int nK = K / 64;
    load_tile(0, 0); cp_commit();
    load_tile(1, 64); cp_commit();
    load_tile(2, 128); cp_commit();
    cp_wait<1>();          // own groups 0,1 done
    __syncthreads();       // all warps' groups 0,1 done

    for (int tt = 0; tt < nK; tt++) {
        if (tt >= 2) bar_sync_id(((tt - 2) & 3) + 1, 512);   // data: all groups <= tt done

        uint32_t sa = sbase + (tt & 3) * WSTAGE;
        uint32_t sb = sa + 16384;

        ld_frags(0, sa, sb, 0);
        #pragma unroll
        for (int G = 0; G < 4; G++) {
            if (G < 3) ld_frags((G + 1) & 1, sa, sb, G + 1);
            const int cur = G & 1;
            #pragma unroll
            for (int mi = 0; mi < 4; mi++)
                #pragma unroll
                for (int ni = 0; ni < 8; ni++)
                    mma_f16(acc[mi][ni], afr[cur][mi], &bfr[cur][ni >> 1][(ni & 1) * 2]);
        }

        if (tt >= 1) bar_sync_id(((tt - 1) & 3) + 5, 512);   // overwrite safety

        if (tt + 3 < nK) {
            load_tile((tt + 3) & 3, (tt + 3) * 64);
            cp_commit();
            cp_wait<1>();          // own groups <= tt+2 done (certification)
        } else {
            cp_wait<0>();
        }
        bar_arrive_id((tt & 3) + 1, 512);
        bar_arrive_id((tt & 3) + 5, 512);
    }

    // ---------------- epilogue (gmem only; no smem reuse -> no barrier) ------
    const __half* selfb = selfg + (long long)b * sSelfb;
    #pragma unroll
    for (int mi = 0; mi < 4; mi++) {
        #pragma unroll
        for (int rr = 0; rr < 2; rr++) {
            int m_loc = mW + mi * 16 + gr + rr * 8;
            long long m = m0 + m_loc;
            float d = ds[(long long)b * NNODE + m];
            #pragma unroll
            for (int ni = 0; ni < 8; ni++) {
                int col = n0 + nW + ni * 8 + 2 * t;
                float v0 = acc[mi][ni][rr * 2 + 0];
                float v1 = acc[mi][ni][rr * 2 + 1];
                float2 sv = __half22float2(*(const __half2*)(selfb + m * ldself + col));
                if (EPI == 0) {
                    v0 = d * (v0 + sv.x);
                    v1 = d * (v1 + sv.y);
                    __half* Ch = (__half*)Cg + (long long)b * sCb;
                    *(__half2*)(Ch + m * ldc + col) = __floats2half2_rn(v0, v1);
                } else {  // EPI == 3
                    v0 = fmaf(d, v0 + sv.x, bias[col]);
                    v1 = fmaf(d, v1 + sv.y, bias[col + 1]);
                    float* Cf = (float*)Cg + (long long)b * sCb;
                    *(float2*)(Cf + m * ldc + col) = make_float2(v0, v1);
                }
            }
        }
    }
}

// ===========================================================================
// FUSED feature kernel (ldsm, rebalanced): per CTA (128 rows):
//   GEMM1: H = relu(Z1 @ W1^T + b1) in two N=256 chunks, 16 warps of 32x64.
//          Z1 ring 2x16KB (re-streamed per chunk), W1 ring 2x32KB.
//   GEMM2: P2 = ds∘(H @ W2^T), H 8x16KB stages in smem, W2 ring 2x32KB.
// 512 threads, occ 1, smem 224KB.
// ===========================================================================
static constexpr int FZ1 = 0;               // Z1 ring: 2 x 16KB = 32KB
static constexpr int FW  = 32768;           // W ring : 2 x 32KB = 64KB
static constexpr int FH  = 98304;           // H      : 8 x 16KB = 128KB
static constexpr int FSMEM = 229376;        // 224 KB

__global__ void __launch_bounds__(512, 1) gemm_feat(
    const __half* __restrict__ Z1, const __half* __restrict__ W1t,
    const __half* __restrict__ W2t, const float* __restrict__ b1,
    const float* __restrict__ ds,
    __half* __restrict__ P2t, __half* __restrict__ P2) {

    extern __shared__ char smem[];
    const uint32_t sbase = smem_u32(smem);
    const int tid = threadIdx.x;
    const long long m0 = (long long)blockIdx.x * 128;

    const int warp = tid >> 5, lane = tid & 31;
    const int gr = lane >> 2, t = lane & 3;

    const int a_rl = lane & 15;
    const int a_cs = lane >> 4;
    const int b_nl = ((lane >> 4) << 3) + (lane & 7);
    const int b_cs = (lane >> 3) & 1;

    const int mW = (warp >> 2) * 32, nW = (warp & 3) * 64;   // 4x4 of 32x64

    auto loadZ1 = [&](int buf, int kk) {
        #pragma unroll
        for (int i = 0; i < 2; i++) {
            int q = tid + i * 512;             // 1024 chunks (128 rows x 8)
            int r = q >> 3, c = q & 7;
            const __half* g = Z1 + (m0 + r) * INC + kk * 64 + c * 8;
            cp_async16(sbase + FZ1 + buf * 16384 + r * 128 + ((c ^ (r & 7)) << 4), g);
        }
    };
    auto loadW = [&](const __half* Wt, int ldw, int rowbase, int buf, int kk) {
        #pragma unroll
        for (int i = 0; i < 4; i++) {
            int q = tid + i * 512;             // 2048 chunks (256 rows x 8)
            int r = q >> 3, c = q & 7;
            const __half* g = Wt + (size_t)(rowbase + r) * ldw + kk * 64 + c * 8;
            cp_async16(sbase + FW + buf * 32768 + r * 128 + ((c ^ (r & 7)) << 4), g);
        }
    };

    // ================= GEMM1: two N=256 chunks =================
    for (int hc = 0; hc < 2; hc++) {
        float acc[2][8][4];
        #pragma unroll
        for (int mi = 0; mi < 2; mi++)
            #pragma unroll
            for (int ni = 0; ni < 8; ni++)
                #pragma unroll
                for (int e = 0; e < 4; e++) acc[mi][ni][e] = 0.f;

        loadZ1(0, 0); loadW(W1t, INC, hc * 256, 0, 0); cp_commit();

        for (int kk = 0; kk < 4; kk++) {
            if (kk + 1 < 4) {
                loadZ1((kk + 1) & 1, kk + 1);
                loadW(W1t, INC, hc * 256, (kk + 1) & 1, kk + 1);
                cp_commit(); cp_wait<1>();
            } else cp_wait<0>();
            __syncthreads();

            uint32_t sa = sbase + FZ1 + (kk & 1) * 16384;
            uint32_t sb = sbase + FW + (kk & 1) * 32768;
            #pragma unroll
            for (int G = 0; G < 4; G++) {
                const int c0 = 2 * G;
                uint32_t a[2][4], bf[4][4];
                #pragma unroll
                for (int mi = 0; mi < 2; mi++) {
                    int r = mW + mi * 16 + a_rl;
                    int c = c0 + a_cs;
                    ldsm_x4(a[mi], sa + r * 128 + ((c ^ (r & 7)) << 4));
                }
                #pragma unroll
                for (int nj = 0; nj < 4; nj++) {
                    int n = nW + nj * 16 + b_nl;
                    int c = c0 + b_cs;
                    ldsm_x4(bf[nj], sb + n * 128 + ((c ^ (n & 7)) << 4));
                }
                #pragma unroll
                for (int mi = 0; mi < 2; mi++)
                    #pragma unroll
                    for (int ni = 0; ni < 8; ni++)
                        mma_f16(acc[mi][ni], a[mi], &bf[ni >> 1][(ni & 1) * 2]);
            }
            __syncthreads();
        }

        // epilogue: relu+bias -> fp16 -> H stages (plain + swizzle)
        #pragma unroll
        for (int mi = 0; mi < 2; mi++) {
            #pragma unroll
            for (int rr = 0; rr < 2; rr++) {
                int m_loc = mW + mi * 16 + gr + rr * 8;
                #pragma unroll
                for (int ni = 0; ni < 8; ni++) {
                    int nl = nW + ni * 8 + 2 * t;
                    int h = hc * 256 + nl;
                    float2 bb = *(const float2*)(b1 + h);
                    float v0 = fmaxf(acc[mi][ni][rr * 2 + 0] + bb.x, 0.f);
                    float v1 = fmaxf(acc[mi][ni][rr * 2 + 1] + bb.y, 0.f);
                    __half2 hv = __floats2half2_rn(v0, v1);
                    int sH = h >> 6, k64 = h & 63;
                    int cch = k64 >> 3;
                    uint32_t addr = sbase + FH + sH * 16384 + m_loc * 128
                                  + ((cch ^ (m_loc & 7)) << 4) + (k64 & 7) * 2;
                    asm volatile("st.shared.b32 [%0], %1;"
                                 :: "r"(addr), "r"(*(uint32_t*)&hv));
                }
            }
        }
        __syncthreads();   // H chunk written before Z1/W rings reused
    }

    // ================= GEMM2: P2 = H @ W2^T (K=512) =================
    float acc2[2][8][4];
    #pragma unroll
    for (int mi = 0; mi < 2; mi++)
        #pragma unroll
        for (int ni = 0; ni < 8; ni++)
            #pragma unroll
            for (int e = 0; e < 4; e++) acc2[mi][ni][e] = 0.f;

    loadW(W2t, HIDC, 0, 0, 0); cp_commit();

    for (int kk = 0; kk < 8; kk++) {
        if (kk + 1 < 8) { loadW(W2t, HIDC, 0, (kk + 1) & 1, kk + 1); cp_commit(); cp_wait<1>(); }
        else cp_wait<0>();
        __syncthreads();
        uint32_t sa = sbase + FH + kk * 16384;
        uint32_t sb = sbase + FW + (kk & 1) * 32768;
        #pragma unroll
        for (int G = 0; G < 4; G++) {
            const int c0 = 2 * G;
            uint32_t a[2][4], bf[4][4];
            #pragma unroll
            for (int mi = 0; mi < 2; mi++) {
                int r = mW + mi * 16 + a_rl;
                int c = c0 + a_cs;
                ldsm_x4(a[mi], sa + r * 128 + ((c ^ (r & 7)) << 4));
            }
            #pragma unroll
            for (int nj = 0; nj < 4; nj++) {
                int n = nW + nj * 16 + b_nl;
                int c = c0 + b_cs;
                ldsm_x4(bf[nj], sb + n * 128 + ((c ^ (n & 7)) << 4));
            }
            #pragma unroll
            for (int mi = 0; mi < 2; mi++)
                #pragma unroll
                for (int ni = 0; ni < 8; ni++)
                    mma_f16(acc2[mi][ni], a[mi], &bf[ni >> 1][(ni & 1) * 2]);
        }
        __syncthreads();
    }

    // ---------------- epilogue: P2 plain + staged transpose for P2t ----------
    __half* sT = (__half*)(smem + FH);    // [256][136] halfs, reuses H region
    #pragma unroll
    for (int mi = 0; mi < 2; mi++) {
        #pragma unroll
        for (int rr = 0; rr < 2; rr++) {
            int m_loc = mW + mi * 16 + gr + rr * 8;
            long long m = m0 + m_loc;
            float d = ds[m];
            #pragma unroll
            for (int ni = 0; ni < 8; ni++) {
                int nl = nW + ni * 8 + 2 * t;
                float v0 = d * acc2[mi][ni][rr * 2 + 0];
                float v1 = d * acc2[mi][ni][rr * 2 + 1];
                __half2 hv = __floats2half2_rn(v0, v1);
                *(__half2*)(P2 + m * OUTC + nl) = hv;
                sT[nl * 136 + m_loc] = __low2half(hv);
                sT[(nl + 1) * 136 + m_loc] = __high2half(hv);
            }
        }
    }
    __syncthreads();

    // transposed plain writeout: thread = (n, m-half)
    {
        int n = tid & 255, mh = tid >> 8;
        int b = (int)(m0 >> 12);
        long long m0loc = m0 & 4095;
        __half* Ct = P2t + (size_t)b * OUTC * NNODE + (size_t)n * NNODE + m0loc + mh * 64;
        #pragma unroll
        for (int mg = 0; mg < 4; mg++) {
            __half2 ph[8];
            #pragma unroll
            for (int pp = 0; pp < 8; pp++) {
                int mA = mh * 64 + mg * 16 + 2 * pp;
                ph[pp] = __halves2half2(sT[n * 136 + mA], sT[n * 136 + mA + 1]);
            }
            uint4* dst = (uint4*)(Ct + mg * 16);
            dst[0] = *(uint4*)&ph[0];
            dst[1] = *(uint4*)&ph[4];
        }
    }
}

// ---------------------------------------------------------------------------
// launch
// ---------------------------------------------------------------------------
extern "C" void kernel_launch(void* const* d_in, const int* in_sizes, int n_in,
                              void* d_out, int out_size) {
    const float* x  = (const float*)d_in[0];
    const float* A  = (const float*)d_in[1];
    const float* W1 = (const float*)d_in[2];
    const float* b1 = (const float*)d_in[3];
    const float* W2 = (const float*)d_in[4];
    const float* b2 = (const float*)d_in[5];
    float* out = (float*)d_out;

    float* ds;
    __half *Ar, *xs, *xst, *Z1, *P2t, *P2, *W1t, *W2t;
    cudaGetSymbolAddress((void**)&ds,  g_ds);
    cudaGetSymbolAddress((void**)&Ar,  g_Ar);
    cudaGetSymbolAddress((void**)&xs,  g_xs);
    cudaGetSymbolAddress((void**)&xst, g_xst);
    cudaGetSymbolAddress((void**)&Z1,  g_Z1);
    cudaGetSymbolAddress((void**)&P2t, g_P2t);
    cudaGetSymbolAddress((void**)&P2,  g_P2);
    cudaGetSymbolAddress((void**)&W1t, g_W1t);
    cudaGetSymbolAddress((void**)&W2t, g_W2t);

    cudaFuncSetAttribute(gemm_f16_wide<0>, cudaFuncAttributeMaxDynamicSharedMemorySize, WSMEM);
    cudaFuncSetAttribute(gemm_f16_wide<3>, cudaFuncAttributeMaxDynamicSharedMemorySize, WSMEM);
    cudaFuncSetAttribute(gemm_feat,        cudaFuncAttributeMaxDynamicSharedMemorySize, FSMEM);

    // prep
    prep_A_kernel<<<BATCH * NNODE, 256>>>(A, Ar, ds);
    prep_x_kernel<<<dim3(NNODE / 32, INC / 32, BATCH), 256>>>(x, ds, xs, xst);
    prep_W_both<<<512, 256>>>(W1, W2, W1t, W2t);

    // G1: Z1 = ds∘(A@xs + xs)
    gemm_f16_wide<0><<<dim3(INC / 256, NNODE / 128, BATCH), 256, WSMEM>>>(
        Ar, xst, Z1, xs, ds, nullptr,
        NNODE, NNODE, NNODE, INC, INC,
        (long long)NNODE * NNODE, (long long)INC * NNODE,
        (long long)NNODE * INC, (long long)NNODE * INC);

    // G2+G3 fused
    gemm_feat<<<MT / 128, 512, FSMEM>>>(Z1, W1t, W2t, b1, ds, P2t, P2);

    // G4: out = ds∘(A@P2 + P2) + b2
    gemm_f16_wide<3><<<dim3(OUTC / 256, NNODE / 128, BATCH), 256, WSMEM>>>(
        Ar, P2t, out, P2, ds, b2,
        NNODE, NNODE, NNODE, OUTC, OUTC,
        (long long)NNODE * NNODE, (long long)OUTC * NNODE,
        (long long)NNODE * OUTC, (long long)NNODE * OUTC);
}